// round 1
// baseline (speedup 1.0000x reference)
#include <cuda_runtime.h>
#include <math.h>

#define B_  8
#define N_  1024
#define D_  256
#define H_  4
#define DH_ 64
#define M_  512
#define EPS_ 1e-5f

// ---------------- scratch (device globals; no allocations allowed) ----------
__device__ float g_h[B_*N_*D_];                 // LN output          32 MB
__device__ float g_qkv[B_*N_*3*D_];             // qkv                24 MB
__device__ float g_scores[(size_t)B_*H_*N_*N_]; // attn scores       134 MB
__device__ float g_o[B_*N_*D_];                 // attn out           32 MB
__device__ float g_y[B_*N_*D_];                 // branch output      32 MB
__device__ float g_t1[B_*N_*M_];                // fc1/gelu out       16 MB
__device__ float g_t2[B_*N_*M_];                // conv/bn/gelu out   16 MB
__device__ float g_mean[B_*D_];
__device__ float g_gate[B_*D_];

__device__ __forceinline__ float gelu_exact(float v) {
    return 0.5f * v * (1.f + erff(v * 0.70710678118654752f));
}

// ---------------- generic batched tiled SGEMM -------------------------------
// C = alpha * A @ B(^T) (+bias) (+gelu), 64x64 tile, BK=16, 256 thr, 4x4/thr.
// Batch index z decomposes as b=z/Hdiv, h=z%Hdiv; per-operand (outer,inner)
// element strides give the (b,h) offsets.
template<bool TRANSB, int ACT>
__global__ void gemm_k(const float* __restrict__ A, int lda, long sAo, long sAi,
                       const float* __restrict__ Bm, int ldb, long sBo, long sBi,
                       float* __restrict__ C, int ldc, long sCo, long sCi,
                       const float* __restrict__ bias, int K, int Hdiv, float alpha)
{
    const int BM = 64, BN = 64, BK = 16;
    __shared__ float As[BK][BM + 1];
    __shared__ float Bs[BK][BN + 1];

    int z  = blockIdx.z;
    int bb = z / Hdiv, hh = z % Hdiv;
    A  += (size_t)bb * sAo + (size_t)hh * sAi;
    Bm += (size_t)bb * sBo + (size_t)hh * sBi;
    C  += (size_t)bb * sCo + (size_t)hh * sCi;

    int m0 = blockIdx.y * BM;
    int n0 = blockIdx.x * BN;
    int tid = threadIdx.x;
    int tx = tid & 15, ty = tid >> 4;

    float acc[4][4] = {};

    for (int k0 = 0; k0 < K; k0 += BK) {
        #pragma unroll
        for (int i = 0; i < 4; i++) {
            int id = tid * 4 + i;
            int m = id >> 4, k = id & 15;
            As[k][m] = A[(size_t)(m0 + m) * lda + k0 + k];
        }
        #pragma unroll
        for (int i = 0; i < 4; i++) {
            int id = tid * 4 + i;
            if (TRANSB) {
                int n = id >> 4, k = id & 15;
                Bs[k][n] = Bm[(size_t)(n0 + n) * ldb + k0 + k];
            } else {
                int k = id >> 6, n = id & 63;
                Bs[k][n] = Bm[(size_t)(k0 + k) * ldb + n0 + n];
            }
        }
        __syncthreads();
        #pragma unroll
        for (int kk = 0; kk < BK; kk++) {
            float a[4], bv[4];
            #pragma unroll
            for (int i = 0; i < 4; i++) a[i] = As[kk][ty * 4 + i];
            #pragma unroll
            for (int j = 0; j < 4; j++) bv[j] = Bs[kk][tx * 4 + j];
            #pragma unroll
            for (int i = 0; i < 4; i++)
                #pragma unroll
                for (int j = 0; j < 4; j++)
                    acc[i][j] += a[i] * bv[j];
        }
        __syncthreads();
    }

    #pragma unroll
    for (int i = 0; i < 4; i++) {
        int m = m0 + ty * 4 + i;
        #pragma unroll
        for (int j = 0; j < 4; j++) {
            int n = n0 + tx * 4 + j;
            float v = acc[i][j] * alpha;
            if (bias) v += bias[n];
            if (ACT == 1) v = gelu_exact(v);
            C[(size_t)m * ldc + n] = v;
        }
    }
}

// ---------------- layernorm: one block per row of 256 -----------------------
__global__ void ln_k(const float* __restrict__ x, const float* __restrict__ g,
                     const float* __restrict__ b, float* __restrict__ out)
{
    int row = blockIdx.x, tid = threadIdx.x;
    __shared__ float s[256];
    float v = x[(size_t)row * D_ + tid];
    s[tid] = v; __syncthreads();
    for (int st = 128; st > 0; st >>= 1) { if (tid < st) s[tid] += s[tid + st]; __syncthreads(); }
    float mu = s[0] * (1.f / D_);
    __syncthreads();
    float d = v - mu;
    s[tid] = d * d; __syncthreads();
    for (int st = 128; st > 0; st >>= 1) { if (tid < st) s[tid] += s[tid + st]; __syncthreads(); }
    float var = s[0] * (1.f / D_);
    out[(size_t)row * D_ + tid] = d * rsqrtf(var + EPS_) * g[tid] + b[tid];
}

// ---------------- row softmax over width 1024 -------------------------------
__global__ void softmax_k(float* __restrict__ S)
{
    size_t row = blockIdx.x;
    float* p = S + row * N_;
    int tid = threadIdx.x;
    __shared__ float s[256];
    float v[4];
    float mx = -3.4e38f;
    #pragma unroll
    for (int i = 0; i < 4; i++) { v[i] = p[tid + i * 256]; mx = fmaxf(mx, v[i]); }
    s[tid] = mx; __syncthreads();
    for (int st = 128; st > 0; st >>= 1) { if (tid < st) s[tid] = fmaxf(s[tid], s[tid + st]); __syncthreads(); }
    mx = s[0]; __syncthreads();
    float sum = 0.f;
    #pragma unroll
    for (int i = 0; i < 4; i++) { v[i] = expf(v[i] - mx); sum += v[i]; }
    s[tid] = sum; __syncthreads();
    for (int st = 128; st > 0; st >>= 1) { if (tid < st) s[tid] += s[tid + st]; __syncthreads(); }
    float inv = 1.f / s[0];
    #pragma unroll
    for (int i = 0; i < 4; i++) p[tid + i * 256] = v[i] * inv;
}

// ---------------- elementwise helpers ---------------------------------------
__global__ void copy_k(const float* __restrict__ src, float* __restrict__ dst)
{
    int idx = blockIdx.x * 256 + threadIdx.x;
    dst[idx] = src[idx];
}

__global__ void add_k(float* __restrict__ x, const float* __restrict__ y)
{
    int idx = blockIdx.x * 256 + threadIdx.x;
    x[idx] += y[idx];
}

__global__ void zero_k(float* __restrict__ p, int n)
{
    int idx = blockIdx.x * 256 + threadIdx.x;
    if (idx < n) p[idx] = 0.f;
}

// partial column sums over token chunks; grid = B_ * (N_/128)
__global__ void colsum_k(const float* __restrict__ z, float* __restrict__ meanbuf)
{
    int b  = blockIdx.x >> 3;
    int n0 = (blockIdx.x & 7) * 128;
    int d  = threadIdx.x;
    const float* p = z + ((size_t)b * N_ + n0) * D_ + d;
    float acc = 0.f;
    #pragma unroll 8
    for (int r = 0; r < 128; r++) acc += p[(size_t)r * D_];
    atomicAdd(&meanbuf[b * D_ + d], acc);
}

// SE gate: s = sigmoid(relu(mean @ w1) @ w2); one block per batch
__global__ void gate_k(const float* __restrict__ meanbuf, const float* __restrict__ w1,
                       const float* __restrict__ w2, float* __restrict__ gatebuf)
{
    int b = blockIdx.x, tid = threadIdx.x;
    __shared__ float m[D_];
    __shared__ float t[D_ / 4];
    m[tid] = meanbuf[b * D_ + tid] * (1.f / N_);
    __syncthreads();
    if (tid < D_ / 4) {
        float acc = 0.f;
        #pragma unroll 8
        for (int d = 0; d < D_; d++) acc += m[d] * w1[d * (D_ / 4) + tid];
        t[tid] = fmaxf(acc, 0.f);
    }
    __syncthreads();
    float acc = 0.f;
    #pragma unroll 8
    for (int j = 0; j < D_ / 4; j++) acc += t[j] * w2[j * D_ + tid];
    gatebuf[b * D_ + tid] = 1.f / (1.f + expf(-acc));
}

__global__ void scale_k(float* __restrict__ x, const float* __restrict__ gate)
{
    int idx = blockIdx.x * 256 + threadIdx.x;
    int d = idx & (D_ - 1);
    int b = idx / (N_ * D_);
    x[idx] *= gate[b * D_ + d];
}

// depthwise 1x3 conv over tokens + center-tap conv + BN(eval) + exact gelu
__global__ void conv_k(const float* __restrict__ y, const float* __restrict__ wh,
                       const float* __restrict__ bh, const float* __restrict__ wv,
                       const float* __restrict__ bv, const float* __restrict__ bng,
                       const float* __restrict__ bnb, const float* __restrict__ bnm,
                       const float* __restrict__ bnv, float* __restrict__ out)
{
    int idx = blockIdx.x * 256 + threadIdx.x;
    int m = idx & (M_ - 1);
    int n = (idx / M_) & (N_ - 1);
    float y0 = y[idx];
    float ym = (n > 0)      ? y[idx - M_] : 0.f;
    float yp = (n < N_ - 1) ? y[idx + M_] : 0.f;
    float ch = wh[m * 3 + 0] * ym + wh[m * 3 + 1] * y0 + wh[m * 3 + 2] * yp + bh[m];
    float cv = wv[m * 3 + 1] * y0 + bv[m];
    float zz = ch + cv;
    zz = (zz - bnm[m]) * rsqrtf(bnv[m] + EPS_) * bng[m] + bnb[m];
    out[idx] = gelu_exact(zz);
}

// ---------------- driver -----------------------------------------------------
static void lsrc_seq(float* X, float* py, float* pmean, float* pgate,
                     const float* w1l, const float* w2l)
{
    add_k<<<(B_*N_*D_)/256, 256>>>(X, py);
    zero_k<<<(B_*D_ + 255)/256, 256>>>(pmean, B_*D_);
    colsum_k<<<B_ * (N_/128), 256>>>(X, pmean);
    gate_k<<<B_, 256>>>(pmean, w1l, w2l, pgate);
    scale_k<<<(B_*N_*D_)/256, 256>>>(X, pgate);
}

extern "C" void kernel_launch(void* const* d_in, const int* in_sizes, int n_in,
                              void* d_out, int out_size)
{
    const float* x_in  = (const float*)d_in[0];
    const float* ln1_g = (const float*)d_in[1];
    const float* ln1_b = (const float*)d_in[2];
    const float* w_qkv = (const float*)d_in[3];
    const float* w_out = (const float*)d_in[4];
    const float* b_out = (const float*)d_in[5];
    const float* ln2_g = (const float*)d_in[6];
    const float* ln2_b = (const float*)d_in[7];
    const float* w_fc1 = (const float*)d_in[8];
    const float* b_fc1 = (const float*)d_in[9];
    const float* wh    = (const float*)d_in[10];
    const float* bh    = (const float*)d_in[11];
    const float* wv    = (const float*)d_in[12];
    const float* bv    = (const float*)d_in[13];
    const float* bn_g  = (const float*)d_in[14];
    const float* bn_b  = (const float*)d_in[15];
    const float* bn_m  = (const float*)d_in[16];
    const float* bn_v  = (const float*)d_in[17];
    const float* w_fc2 = (const float*)d_in[18];
    const float* b_fc2 = (const float*)d_in[19];
    const float* ls_w1 = (const float*)d_in[20];
    const float* ls_w2 = (const float*)d_in[21];

    float *ph, *pqkv, *ps, *po, *py, *pt1, *pt2, *pmean, *pgate;
    cudaGetSymbolAddress((void**)&ph,    g_h);
    cudaGetSymbolAddress((void**)&pqkv,  g_qkv);
    cudaGetSymbolAddress((void**)&ps,    g_scores);
    cudaGetSymbolAddress((void**)&po,    g_o);
    cudaGetSymbolAddress((void**)&py,    g_y);
    cudaGetSymbolAddress((void**)&pt1,   g_t1);
    cudaGetSymbolAddress((void**)&pt2,   g_t2);
    cudaGetSymbolAddress((void**)&pmean, g_mean);
    cudaGetSymbolAddress((void**)&pgate, g_gate);

    float* X = (float*)d_out;
    const int ROWS = B_ * N_;   // 8192

    copy_k<<<(B_*N_*D_)/256, 256>>>(x_in, X);

    for (int l = 0; l < 2; l++) {
        const float* w_qkv_l = w_qkv + (size_t)l * D_ * 3 * D_;
        const float* w_out_l = w_out + (size_t)l * D_ * D_;
        const float* b_out_l = b_out + (size_t)l * D_;
        const float* w_fc1_l = w_fc1 + (size_t)l * D_ * M_;
        const float* b_fc1_l = b_fc1 + (size_t)l * M_;
        const float* w_fc2_l = w_fc2 + (size_t)l * M_ * D_;
        const float* b_fc2_l = b_fc2 + (size_t)l * D_;
        const float* w1_l    = ls_w1 + (size_t)l * D_ * (D_/4);
        const float* w2_l    = ls_w2 + (size_t)l * (D_/4) * D_;

        // --- MHSA ---
        ln_k<<<ROWS, 256>>>(X, ln1_g + l * D_, ln1_b + l * D_, ph);

        // qkv = h @ w_qkv   [8192,256]x[256,768]
        gemm_k<false, 0><<<dim3((3*D_)/64, ROWS/64, 1), 256>>>(
            ph, D_, 0, 0, w_qkv_l, 3*D_, 0, 0, pqkv, 3*D_, 0, 0,
            nullptr, D_, 1, 1.f);

        // scores = scale * q @ k^T, batched over (b,h)
        gemm_k<true, 0><<<dim3(N_/64, N_/64, B_*H_), 256>>>(
            pqkv,        3*D_, (long)N_*3*D_, DH_,
            pqkv + D_,   3*D_, (long)N_*3*D_, DH_,
            ps,          N_,   (long)H_*N_*N_, (long)N_*N_,
            nullptr, DH_, H_, 0.125f);

        softmax_k<<<B_*H_*N_, 256>>>(ps);

        // o = P @ v
        gemm_k<false, 0><<<dim3(DH_/64, N_/64, B_*H_), 256>>>(
            ps,          N_,   (long)H_*N_*N_, (long)N_*N_,
            pqkv + 2*D_, 3*D_, (long)N_*3*D_, DH_,
            po,          D_,   (long)N_*D_,   DH_,
            nullptr, N_, H_, 1.f);

        // y = o @ w_out + b_out
        gemm_k<false, 0><<<dim3(D_/64, ROWS/64, 1), 256>>>(
            po, D_, 0, 0, w_out_l, D_, 0, 0, py, D_, 0, 0,
            b_out_l, D_, 1, 1.f);

        lsrc_seq(X, py, pmean, pgate, w1_l, w2_l);

        // --- MLP ---
        ln_k<<<ROWS, 256>>>(X, ln2_g + l * D_, ln2_b + l * D_, ph);

        // t1 = gelu(h @ w_fc1 + b_fc1)
        gemm_k<false, 1><<<dim3(M_/64, ROWS/64, 1), 256>>>(
            ph, D_, 0, 0, w_fc1_l, M_, 0, 0, pt1, M_, 0, 0,
            b_fc1_l, D_, 1, 1.f);

        // conv + BN + gelu
        conv_k<<<(B_*N_*M_)/256, 256>>>(
            pt1, wh + (size_t)l*M_*3, bh + (size_t)l*M_,
            wv + (size_t)l*M_*3, bv + (size_t)l*M_,
            bn_g + (size_t)l*M_, bn_b + (size_t)l*M_,
            bn_m + (size_t)l*M_, bn_v + (size_t)l*M_, pt2);

        // y = t2 @ w_fc2 + b_fc2
        gemm_k<false, 0><<<dim3(D_/64, ROWS/64, 1), 256>>>(
            pt2, M_, 0, 0, w_fc2_l, D_, 0, 0, py, D_, 0, 0,
            b_fc2_l, M_, 1, 1.f);

        lsrc_seq(X, py, pmean, pgate, w1_l, w2_l);
    }
}

// round 2
// speedup vs baseline: 1.5330x; 1.5330x over previous
#include <cuda_runtime.h>
#include <math.h>

#define B_  8
#define N_  1024
#define D_  256
#define H_  4
#define DH_ 64
#define M_  512
#define EPS_ 1e-5f

// ---------------- scratch (device globals; no allocations allowed) ----------
__device__ float g_h[B_*N_*D_];                 // LN output
__device__ float g_qkv[B_*N_*3*D_];             // qkv
__device__ float g_scores[(size_t)B_*H_*N_*N_]; // attn scores (134 MB)
__device__ float g_o[B_*N_*D_];                 // attn out
__device__ float g_y[B_*N_*D_];                 // branch output
__device__ float g_t1[B_*N_*M_];                // fc1/gelu out
__device__ float g_t2[B_*N_*M_];                // conv/bn/gelu out
__device__ float g_mean[B_*D_];
__device__ float g_gate[B_*D_];

__device__ __forceinline__ float gelu_exact(float v) {
    return 0.5f * v * (1.f + erff(v * 0.70710678118654752f));
}

// ---------------- batched tiled SGEMM v2 ------------------------------------
// C = alpha * A @ B(^T) (+bias) (+gelu).
// BM x BN tile, BK=16, TM x TN per thread, double-buffered smem with
// register prefetch, float4 global loads (all operand strides are multiples
// of 4 floats in this problem).
template<int BM, int BN, int TM, int TN, bool TRANSB, int ACT>
__global__ __launch_bounds__((BM/TM)*(BN/TN))
void gemm2_k(const float* __restrict__ A, int lda, long sAo, long sAi,
             const float* __restrict__ Bm, int ldb, long sBo, long sBi,
             float* __restrict__ C, int ldc, long sCo, long sCi,
             const float* __restrict__ bias, int K, int Hdiv, float alpha)
{
    constexpr int BK = 16;
    constexpr int NT = (BM/TM)*(BN/TN);
    constexpr int VA = BM*4/NT;                      // float4 A-loads / thread
    constexpr int VB = TRANSB ? BN*4/NT : BK*BN/4/NT;
    constexpr int TX = BN/TN;

    __shared__ float As[2][BK][BM];
    __shared__ float Bs[2][BK][BN];

    int z  = blockIdx.z;
    int bb = z / Hdiv, hh = z % Hdiv;
    A  += (size_t)bb * sAo + (size_t)hh * sAi;
    Bm += (size_t)bb * sBo + (size_t)hh * sBi;
    C  += (size_t)bb * sCo + (size_t)hh * sCi;

    const int m0 = blockIdx.y * BM;
    const int n0 = blockIdx.x * BN;
    const int tid = threadIdx.x;
    const int tx = tid % TX, ty = tid / TX;

    float4 ra[VA], rb[VB];

    auto ldg = [&](int k0) {
        #pragma unroll
        for (int i = 0; i < VA; i++) {
            int v = tid + i * NT;
            int m = v >> 2, kq = v & 3;
            ra[i] = *(const float4*)&A[(size_t)(m0 + m) * lda + k0 + kq * 4];
        }
        #pragma unroll
        for (int i = 0; i < VB; i++) {
            int v = tid + i * NT;
            if (TRANSB) {
                int n = v >> 2, kq = v & 3;
                rb[i] = *(const float4*)&Bm[(size_t)(n0 + n) * ldb + k0 + kq * 4];
            } else {
                int k = v / (BN / 4), nq = v % (BN / 4);
                rb[i] = *(const float4*)&Bm[(size_t)(k0 + k) * ldb + n0 + nq * 4];
            }
        }
    };
    auto sts = [&](int buf) {
        #pragma unroll
        for (int i = 0; i < VA; i++) {
            int v = tid + i * NT;
            int m = v >> 2, kq = v & 3;
            As[buf][kq * 4 + 0][m] = ra[i].x;
            As[buf][kq * 4 + 1][m] = ra[i].y;
            As[buf][kq * 4 + 2][m] = ra[i].z;
            As[buf][kq * 4 + 3][m] = ra[i].w;
        }
        #pragma unroll
        for (int i = 0; i < VB; i++) {
            int v = tid + i * NT;
            if (TRANSB) {
                int n = v >> 2, kq = v & 3;
                Bs[buf][kq * 4 + 0][n] = rb[i].x;
                Bs[buf][kq * 4 + 1][n] = rb[i].y;
                Bs[buf][kq * 4 + 2][n] = rb[i].z;
                Bs[buf][kq * 4 + 3][n] = rb[i].w;
            } else {
                int k = v / (BN / 4), nq = v % (BN / 4);
                *(float4*)&Bs[buf][k][nq * 4] = rb[i];
            }
        }
    };

    float acc[TM][TN] = {};

    ldg(0); sts(0); __syncthreads();
    int cur = 0;
    for (int k0 = 0; k0 < K; k0 += BK) {
        bool more = (k0 + BK) < K;
        if (more) ldg(k0 + BK);
        #pragma unroll
        for (int kk = 0; kk < BK; kk++) {
            float af[TM], bf[TN];
            #pragma unroll
            for (int i = 0; i < TM; i += 4)
                *(float4*)&af[i] = *(const float4*)&As[cur][kk][ty * TM + i];
            #pragma unroll
            for (int j = 0; j < TN; j += 4)
                *(float4*)&bf[j] = *(const float4*)&Bs[cur][kk][tx * TN + j];
            #pragma unroll
            for (int i = 0; i < TM; i++)
                #pragma unroll
                for (int j = 0; j < TN; j++)
                    acc[i][j] += af[i] * bf[j];
        }
        if (more) { sts(cur ^ 1); __syncthreads(); cur ^= 1; }
    }

    #pragma unroll
    for (int i = 0; i < TM; i++) {
        int m = m0 + ty * TM + i;
        #pragma unroll
        for (int j = 0; j < TN; j += 4) {
            int n = n0 + tx * TN + j;
            float4 v;
            v.x = acc[i][j + 0] * alpha;
            v.y = acc[i][j + 1] * alpha;
            v.z = acc[i][j + 2] * alpha;
            v.w = acc[i][j + 3] * alpha;
            if (bias) {
                v.x += bias[n]; v.y += bias[n + 1];
                v.z += bias[n + 2]; v.w += bias[n + 3];
            }
            if (ACT == 1) {
                v.x = gelu_exact(v.x); v.y = gelu_exact(v.y);
                v.z = gelu_exact(v.z); v.w = gelu_exact(v.w);
            }
            *(float4*)&C[(size_t)m * ldc + n] = v;
        }
    }
}

// ---------------- layernorm: one block per row of 256 -----------------------
__global__ void ln_k(const float* __restrict__ x, const float* __restrict__ g,
                     const float* __restrict__ b, float* __restrict__ out)
{
    int row = blockIdx.x, tid = threadIdx.x;
    __shared__ float s[256];
    float v = x[(size_t)row * D_ + tid];
    s[tid] = v; __syncthreads();
    for (int st = 128; st > 0; st >>= 1) { if (tid < st) s[tid] += s[tid + st]; __syncthreads(); }
    float mu = s[0] * (1.f / D_);
    __syncthreads();
    float d = v - mu;
    s[tid] = d * d; __syncthreads();
    for (int st = 128; st > 0; st >>= 1) { if (tid < st) s[tid] += s[tid + st]; __syncthreads(); }
    float var = s[0] * (1.f / D_);
    out[(size_t)row * D_ + tid] = d * rsqrtf(var + EPS_) * g[tid] + b[tid];
}

// ---------------- row softmax over width 1024 -------------------------------
__global__ void softmax_k(float* __restrict__ S)
{
    size_t row = blockIdx.x;
    float* p = S + row * N_;
    int tid = threadIdx.x;
    __shared__ float s[256];
    float v[4];
    float mx = -3.4e38f;
    #pragma unroll
    for (int i = 0; i < 4; i++) { v[i] = p[tid + i * 256]; mx = fmaxf(mx, v[i]); }
    s[tid] = mx; __syncthreads();
    for (int st = 128; st > 0; st >>= 1) { if (tid < st) s[tid] = fmaxf(s[tid], s[tid + st]); __syncthreads(); }
    mx = s[0]; __syncthreads();
    float sum = 0.f;
    #pragma unroll
    for (int i = 0; i < 4; i++) { v[i] = expf(v[i] - mx); sum += v[i]; }
    s[tid] = sum; __syncthreads();
    for (int st = 128; st > 0; st >>= 1) { if (tid < st) s[tid] += s[tid + st]; __syncthreads(); }
    float inv = 1.f / s[0];
    #pragma unroll
    for (int i = 0; i < 4; i++) p[tid + i * 256] = v[i] * inv;
}

// ---------------- elementwise helpers ---------------------------------------
__global__ void copy_k(const float* __restrict__ src, float* __restrict__ dst)
{
    int idx = blockIdx.x * 256 + threadIdx.x;
    dst[idx] = src[idx];
}

__global__ void add_k(float* __restrict__ x, const float* __restrict__ y)
{
    int idx = blockIdx.x * 256 + threadIdx.x;
    x[idx] += y[idx];
}

__global__ void zero_k(float* __restrict__ p, int n)
{
    int idx = blockIdx.x * 256 + threadIdx.x;
    if (idx < n) p[idx] = 0.f;
}

// partial column sums over token chunks; grid = B_ * (N_/128)
__global__ void colsum_k(const float* __restrict__ z, float* __restrict__ meanbuf)
{
    int b  = blockIdx.x >> 3;
    int n0 = (blockIdx.x & 7) * 128;
    int d  = threadIdx.x;
    const float* p = z + ((size_t)b * N_ + n0) * D_ + d;
    float acc = 0.f;
    #pragma unroll 8
    for (int r = 0; r < 128; r++) acc += p[(size_t)r * D_];
    atomicAdd(&meanbuf[b * D_ + d], acc);
}

// SE gate: s = sigmoid(relu(mean @ w1) @ w2); one block per batch
__global__ void gate_k(const float* __restrict__ meanbuf, const float* __restrict__ w1,
                       const float* __restrict__ w2, float* __restrict__ gatebuf)
{
    int b = blockIdx.x, tid = threadIdx.x;
    __shared__ float m[D_];
    __shared__ float t[D_ / 4];
    m[tid] = meanbuf[b * D_ + tid] * (1.f / N_);
    __syncthreads();
    if (tid < D_ / 4) {
        float acc = 0.f;
        #pragma unroll 8
        for (int d = 0; d < D_; d++) acc += m[d] * w1[d * (D_ / 4) + tid];
        t[tid] = fmaxf(acc, 0.f);
    }
    __syncthreads();
    float acc = 0.f;
    #pragma unroll 8
    for (int j = 0; j < D_ / 4; j++) acc += t[j] * w2[j * D_ + tid];
    gatebuf[b * D_ + tid] = 1.f / (1.f + expf(-acc));
}

__global__ void scale_k(float* __restrict__ x, const float* __restrict__ gate)
{
    int idx = blockIdx.x * 256 + threadIdx.x;
    int d = idx & (D_ - 1);
    int b = idx / (N_ * D_);
    x[idx] *= gate[b * D_ + d];
}

// depthwise 1x3 conv over tokens + center-tap conv + BN(eval) + exact gelu
__global__ void conv_k(const float* __restrict__ y, const float* __restrict__ wh,
                       const float* __restrict__ bh, const float* __restrict__ wv,
                       const float* __restrict__ bv, const float* __restrict__ bng,
                       const float* __restrict__ bnb, const float* __restrict__ bnm,
                       const float* __restrict__ bnv, float* __restrict__ out)
{
    int idx = blockIdx.x * 256 + threadIdx.x;
    int m = idx & (M_ - 1);
    int n = (idx / M_) & (N_ - 1);
    float y0 = y[idx];
    float ym = (n > 0)      ? y[idx - M_] : 0.f;
    float yp = (n < N_ - 1) ? y[idx + M_] : 0.f;
    float ch = wh[m * 3 + 0] * ym + wh[m * 3 + 1] * y0 + wh[m * 3 + 2] * yp + bh[m];
    float cv = wv[m * 3 + 1] * y0 + bv[m];
    float zz = ch + cv;
    zz = (zz - bnm[m]) * rsqrtf(bnv[m] + EPS_) * bng[m] + bnb[m];
    out[idx] = gelu_exact(zz);
}

// ---------------- driver -----------------------------------------------------
static void lsrc_seq(float* X, float* py, float* pmean, float* pgate,
                     const float* w1l, const float* w2l)
{
    add_k<<<(B_*N_*D_)/256, 256>>>(X, py);
    zero_k<<<(B_*D_ + 255)/256, 256>>>(pmean, B_*D_);
    colsum_k<<<B_ * (N_/128), 256>>>(X, pmean);
    gate_k<<<B_, 256>>>(pmean, w1l, w2l, pgate);
    scale_k<<<(B_*N_*D_)/256, 256>>>(X, pgate);
}

extern "C" void kernel_launch(void* const* d_in, const int* in_sizes, int n_in,
                              void* d_out, int out_size)
{
    const float* x_in  = (const float*)d_in[0];
    const float* ln1_g = (const float*)d_in[1];
    const float* ln1_b = (const float*)d_in[2];
    const float* w_qkv = (const float*)d_in[3];
    const float* w_out = (const float*)d_in[4];
    const float* b_out = (const float*)d_in[5];
    const float* ln2_g = (const float*)d_in[6];
    const float* ln2_b = (const float*)d_in[7];
    const float* w_fc1 = (const float*)d_in[8];
    const float* b_fc1 = (const float*)d_in[9];
    const float* wh    = (const float*)d_in[10];
    const float* bh    = (const float*)d_in[11];
    const float* wv    = (const float*)d_in[12];
    const float* bv    = (const float*)d_in[13];
    const float* bn_g  = (const float*)d_in[14];
    const float* bn_b  = (const float*)d_in[15];
    const float* bn_m  = (const float*)d_in[16];
    const float* bn_v  = (const float*)d_in[17];
    const float* w_fc2 = (const float*)d_in[18];
    const float* b_fc2 = (const float*)d_in[19];
    const float* ls_w1 = (const float*)d_in[20];
    const float* ls_w2 = (const float*)d_in[21];

    float *ph, *pqkv, *ps, *po, *py, *pt1, *pt2, *pmean, *pgate;
    cudaGetSymbolAddress((void**)&ph,    g_h);
    cudaGetSymbolAddress((void**)&pqkv,  g_qkv);
    cudaGetSymbolAddress((void**)&ps,    g_scores);
    cudaGetSymbolAddress((void**)&po,    g_o);
    cudaGetSymbolAddress((void**)&py,    g_y);
    cudaGetSymbolAddress((void**)&pt1,   g_t1);
    cudaGetSymbolAddress((void**)&pt2,   g_t2);
    cudaGetSymbolAddress((void**)&pmean, g_mean);
    cudaGetSymbolAddress((void**)&pgate, g_gate);

    float* X = (float*)d_out;
    const int ROWS = B_ * N_;   // 8192

    copy_k<<<(B_*N_*D_)/256, 256>>>(x_in, X);

    for (int l = 0; l < 2; l++) {
        const float* w_qkv_l = w_qkv + (size_t)l * D_ * 3 * D_;
        const float* w_out_l = w_out + (size_t)l * D_ * D_;
        const float* b_out_l = b_out + (size_t)l * D_;
        const float* w_fc1_l = w_fc1 + (size_t)l * D_ * M_;
        const float* b_fc1_l = b_fc1 + (size_t)l * M_;
        const float* w_fc2_l = w_fc2 + (size_t)l * M_ * D_;
        const float* b_fc2_l = b_fc2 + (size_t)l * D_;
        const float* w1_l    = ls_w1 + (size_t)l * D_ * (D_/4);
        const float* w2_l    = ls_w2 + (size_t)l * (D_/4) * D_;

        // --- MHSA ---
        ln_k<<<ROWS, 256>>>(X, ln1_g + l * D_, ln1_b + l * D_, ph);

        // qkv = h @ w_qkv   [8192,256]x[256,768]
        gemm2_k<128,128,8,8,false,0><<<dim3((3*D_)/128, ROWS/128, 1), 256>>>(
            ph, D_, 0, 0, w_qkv_l, 3*D_, 0, 0, pqkv, 3*D_, 0, 0,
            nullptr, D_, 1, 1.f);

        // scores = scale * q @ k^T, batched over (b,h)
        gemm2_k<128,128,8,8,true,0><<<dim3(N_/128, N_/128, B_*H_), 256>>>(
            pqkv,        3*D_, (long)N_*3*D_, DH_,
            pqkv + D_,   3*D_, (long)N_*3*D_, DH_,
            ps,          N_,   (long)H_*N_*N_, (long)N_*N_,
            nullptr, DH_, H_, 0.125f);

        softmax_k<<<B_*H_*N_, 256>>>(ps);

        // o = P @ v   [1024,1024]x[1024,64] per (b,h)
        gemm2_k<128,64,8,8,false,0><<<dim3(1, N_/128, B_*H_), 128>>>(
            ps,          N_,   (long)H_*N_*N_, (long)N_*N_,
            pqkv + 2*D_, 3*D_, (long)N_*3*D_, DH_,
            po,          D_,   (long)N_*D_,   DH_,
            nullptr, N_, H_, 1.f);

        // y = o @ w_out + b_out
        gemm2_k<128,128,8,8,false,0><<<dim3(D_/128, ROWS/128, 1), 256>>>(
            po, D_, 0, 0, w_out_l, D_, 0, 0, py, D_, 0, 0,
            b_out_l, D_, 1, 1.f);

        lsrc_seq(X, py, pmean, pgate, w1_l, w2_l);

        // --- MLP ---
        ln_k<<<ROWS, 256>>>(X, ln2_g + l * D_, ln2_b + l * D_, ph);

        // t1 = gelu(h @ w_fc1 + b_fc1)
        gemm2_k<128,128,8,8,false,1><<<dim3(M_/128, ROWS/128, 1), 256>>>(
            ph, D_, 0, 0, w_fc1_l, M_, 0, 0, pt1, M_, 0, 0,
            b_fc1_l, D_, 1, 1.f);

        // conv + BN + gelu
        conv_k<<<(B_*N_*M_)/256, 256>>>(
            pt1, wh + (size_t)l*M_*3, bh + (size_t)l*M_,
            wv + (size_t)l*M_*3, bv + (size_t)l*M_,
            bn_g + (size_t)l*M_, bn_b + (size_t)l*M_,
            bn_m + (size_t)l*M_, bn_v + (size_t)l*M_, pt2);

        // y = t2 @ w_fc2 + b_fc2
        gemm2_k<128,128,8,8,false,0><<<dim3(D_/128, ROWS/128, 1), 256>>>(
            pt2, M_, 0, 0, w_fc2_l, D_, 0, 0, py, D_, 0, 0,
            b_fc2_l, M_, 1, 1.f);

        lsrc_seq(X, py, pmean, pgate, w1_l, w2_l);
    }
}

// round 3
// speedup vs baseline: 2.5009x; 1.6314x over previous
#include <cuda_runtime.h>
#include <math.h>
#include <stdint.h>

#define B_  8
#define N_  1024
#define D_  256
#define H_  4
#define DH_ 64
#define M_  512
#define EPS_ 1e-5f

// ---------------- scratch (device globals; no allocations allowed) ----------
__device__ float g_h[B_*N_*D_];                 // LN output
__device__ float g_qkv[B_*N_*3*D_];             // qkv
__device__ float g_scores[(size_t)B_*H_*N_*N_]; // attn scores (134 MB)
__device__ float g_o[B_*N_*D_];                 // attn out
__device__ float g_y[B_*N_*D_];                 // branch output
__device__ float g_t1[B_*N_*M_];                // fc1/gelu out
__device__ float g_t2[B_*N_*M_];                // conv/bn/gelu out
__device__ float g_mean[B_*D_];
__device__ float g_gate[B_*D_];

__device__ __forceinline__ float gelu_exact(float v) {
    return 0.5f * v * (1.f + erff(v * 0.70710678118654752f));
}

__device__ __forceinline__ float to_tf32(float x) {
    uint32_t u;
    asm("cvt.rna.tf32.f32 %0, %1;" : "=r"(u) : "f"(x));
    return __uint_as_float(u);
}

__device__ __forceinline__ void mma_tf32(float& c0, float& c1, float& c2, float& c3,
                                         float a0, float a1, float a2, float a3,
                                         float b0, float b1)
{
    asm volatile(
        "mma.sync.aligned.m16n8k8.row.col.f32.tf32.tf32.f32 "
        "{%0,%1,%2,%3},{%4,%5,%6,%7},{%8,%9},{%0,%1,%2,%3};"
        : "+f"(c0), "+f"(c1), "+f"(c2), "+f"(c3)
        : "r"(__float_as_uint(a0)), "r"(__float_as_uint(a1)),
          "r"(__float_as_uint(a2)), "r"(__float_as_uint(a3)),
          "r"(__float_as_uint(b0)), "r"(__float_as_uint(b1)));
}

// ---------------- batched tensor-core GEMM (tf32) ----------------------------
// C = alpha * A @ B(^T) (+bias) (+gelu).  BMxBN block, BK=16, warp tile WMxWN.
// A tile stored m-major [BM][BK+4]; B tile k-major [BK][BN+8]; pads make all
// fragment LDS bank-conflict free. Double-buffered with register prefetch.
template<int BM, int BN, int WM, int WN, bool TRANSB, int ACT>
__global__ __launch_bounds__((BM/WM)*(BN/WN)*32)
void gemm3_k(const float* __restrict__ A, int lda, long sAo, long sAi,
             const float* __restrict__ Bm, int ldb, long sBo, long sBi,
             float* __restrict__ C, int ldc, long sCo, long sCi,
             const float* __restrict__ bias, int K, int Hdiv, float alpha)
{
    constexpr int BK = 16;
    constexpr int NT  = (BM/WM)*(BN/WN)*32;     // threads
    constexpr int LA  = BM*BK/(4*NT);           // float4 A-loads / thread
    constexpr int LB  = BN*BK/(4*NT);
    constexpr int MT  = WM/16;                  // mma tiles per warp (m)
    constexpr int NTL = WN/8;                   // mma tiles per warp (n)
    constexpr int NWN = BN/WN;

    __shared__ float As[2][BM][BK+4];
    __shared__ float Bs[2][BK][BN+8];

    int z  = blockIdx.z;
    int bb = z / Hdiv, hh = z % Hdiv;
    A  += (size_t)bb * sAo + (size_t)hh * sAi;
    Bm += (size_t)bb * sBo + (size_t)hh * sBi;
    C  += (size_t)bb * sCo + (size_t)hh * sCi;

    const int m0 = blockIdx.y * BM;
    const int n0 = blockIdx.x * BN;
    const int tid   = threadIdx.x;
    const int warp  = tid >> 5;
    const int lane  = tid & 31;
    const int gid   = lane >> 2;    // 0..7
    const int tig   = lane & 3;     // 0..3
    const int warpM = warp / NWN;
    const int warpN = warp % NWN;

    float4 ra[LA], rb[LB];

    auto ldg = [&](int k0) {
        #pragma unroll
        for (int i = 0; i < LA; i++) {
            int v = tid + i * NT;
            int m = v >> 2, kq = v & 3;
            ra[i] = *(const float4*)&A[(size_t)(m0 + m) * lda + k0 + kq * 4];
        }
        #pragma unroll
        for (int i = 0; i < LB; i++) {
            int v = tid + i * NT;
            if (TRANSB) {
                int n = v >> 2, kq = v & 3;
                rb[i] = *(const float4*)&Bm[(size_t)(n0 + n) * ldb + k0 + kq * 4];
            } else {
                int k = v / (BN / 4), nq = v % (BN / 4);
                rb[i] = *(const float4*)&Bm[(size_t)(k0 + k) * ldb + n0 + nq * 4];
            }
        }
    };
    auto sts = [&](int buf) {
        #pragma unroll
        for (int i = 0; i < LA; i++) {
            int v = tid + i * NT;
            int m = v >> 2, kq = v & 3;
            float4 t;
            t.x = to_tf32(ra[i].x); t.y = to_tf32(ra[i].y);
            t.z = to_tf32(ra[i].z); t.w = to_tf32(ra[i].w);
            *(float4*)&As[buf][m][kq * 4] = t;
        }
        #pragma unroll
        for (int i = 0; i < LB; i++) {
            int v = tid + i * NT;
            if (TRANSB) {
                int n = v >> 2, kq = v & 3;
                Bs[buf][kq * 4 + 0][n] = to_tf32(rb[i].x);
                Bs[buf][kq * 4 + 1][n] = to_tf32(rb[i].y);
                Bs[buf][kq * 4 + 2][n] = to_tf32(rb[i].z);
                Bs[buf][kq * 4 + 3][n] = to_tf32(rb[i].w);
            } else {
                int k = v / (BN / 4), nq = v % (BN / 4);
                float4 t;
                t.x = to_tf32(rb[i].x); t.y = to_tf32(rb[i].y);
                t.z = to_tf32(rb[i].z); t.w = to_tf32(rb[i].w);
                *(float4*)&Bs[buf][k][nq * 4] = t;
            }
        }
    };

    float acc[MT][NTL][4];
    #pragma unroll
    for (int i = 0; i < MT; i++)
        #pragma unroll
        for (int j = 0; j < NTL; j++)
            #pragma unroll
            for (int c = 0; c < 4; c++) acc[i][j][c] = 0.f;

    ldg(0); sts(0); __syncthreads();
    int cur = 0;
    for (int k0 = 0; k0 < K; k0 += BK) {
        bool more = (k0 + BK) < K;
        if (more) ldg(k0 + BK);
        #pragma unroll
        for (int ks = 0; ks < BK; ks += 8) {
            float af[MT][4], bf[NTL][2];
            #pragma unroll
            for (int mt = 0; mt < MT; mt++) {
                int rb0 = warpM * WM + mt * 16;
                af[mt][0] = As[cur][rb0 + gid    ][ks + tig];
                af[mt][1] = As[cur][rb0 + gid + 8][ks + tig];
                af[mt][2] = As[cur][rb0 + gid    ][ks + tig + 4];
                af[mt][3] = As[cur][rb0 + gid + 8][ks + tig + 4];
            }
            #pragma unroll
            for (int nt = 0; nt < NTL; nt++) {
                int cb0 = warpN * WN + nt * 8;
                bf[nt][0] = Bs[cur][ks + tig    ][cb0 + gid];
                bf[nt][1] = Bs[cur][ks + tig + 4][cb0 + gid];
            }
            #pragma unroll
            for (int mt = 0; mt < MT; mt++)
                #pragma unroll
                for (int nt = 0; nt < NTL; nt++)
                    mma_tf32(acc[mt][nt][0], acc[mt][nt][1],
                             acc[mt][nt][2], acc[mt][nt][3],
                             af[mt][0], af[mt][1], af[mt][2], af[mt][3],
                             bf[nt][0], bf[nt][1]);
        }
        if (more) { sts(cur ^ 1); __syncthreads(); cur ^= 1; }
    }

    // epilogue: c0/c1 = (row, col), (row, col+1); c2/c3 same at row+8
    #pragma unroll
    for (int mt = 0; mt < MT; mt++) {
        int row = m0 + warpM * WM + mt * 16 + gid;
        #pragma unroll
        for (int nt = 0; nt < NTL; nt++) {
            int col = n0 + warpN * WN + nt * 8 + tig * 2;
            float v0 = acc[mt][nt][0] * alpha;
            float v1 = acc[mt][nt][1] * alpha;
            float v2 = acc[mt][nt][2] * alpha;
            float v3 = acc[mt][nt][3] * alpha;
            if (bias) {
                float b0v = bias[col], b1v = bias[col + 1];
                v0 += b0v; v1 += b1v; v2 += b0v; v3 += b1v;
            }
            if (ACT == 1) {
                v0 = gelu_exact(v0); v1 = gelu_exact(v1);
                v2 = gelu_exact(v2); v3 = gelu_exact(v3);
            }
            *(float2*)&C[(size_t)row * ldc + col]       = make_float2(v0, v1);
            *(float2*)&C[(size_t)(row + 8) * ldc + col] = make_float2(v2, v3);
        }
    }
}

// ---------------- layernorm: one block per row of 256 -----------------------
__global__ void ln_k(const float* __restrict__ x, const float* __restrict__ g,
                     const float* __restrict__ b, float* __restrict__ out)
{
    int row = blockIdx.x, tid = threadIdx.x;
    __shared__ float s[256];
    float v = x[(size_t)row * D_ + tid];
    s[tid] = v; __syncthreads();
    for (int st = 128; st > 0; st >>= 1) { if (tid < st) s[tid] += s[tid + st]; __syncthreads(); }
    float mu = s[0] * (1.f / D_);
    __syncthreads();
    float d = v - mu;
    s[tid] = d * d; __syncthreads();
    for (int st = 128; st > 0; st >>= 1) { if (tid < st) s[tid] += s[tid + st]; __syncthreads(); }
    float var = s[0] * (1.f / D_);
    out[(size_t)row * D_ + tid] = d * rsqrtf(var + EPS_) * g[tid] + b[tid];
}

// ---------------- row softmax over width 1024 -------------------------------
__global__ void softmax_k(float* __restrict__ S)
{
    size_t row = blockIdx.x;
    float* p = S + row * N_;
    int tid = threadIdx.x;
    __shared__ float s[256];
    float v[4];
    float mx = -3.4e38f;
    #pragma unroll
    for (int i = 0; i < 4; i++) { v[i] = p[tid + i * 256]; mx = fmaxf(mx, v[i]); }
    s[tid] = mx; __syncthreads();
    for (int st = 128; st > 0; st >>= 1) { if (tid < st) s[tid] = fmaxf(s[tid], s[tid + st]); __syncthreads(); }
    mx = s[0]; __syncthreads();
    float sum = 0.f;
    #pragma unroll
    for (int i = 0; i < 4; i++) { v[i] = expf(v[i] - mx); sum += v[i]; }
    s[tid] = sum; __syncthreads();
    for (int st = 128; st > 0; st >>= 1) { if (tid < st) s[tid] += s[tid + st]; __syncthreads(); }
    float inv = 1.f / s[0];
    #pragma unroll
    for (int i = 0; i < 4; i++) p[tid + i * 256] = v[i] * inv;
}

// ---------------- elementwise helpers ---------------------------------------
__global__ void copy_k(const float* __restrict__ src, float* __restrict__ dst)
{
    int idx = blockIdx.x * 256 + threadIdx.x;
    dst[idx] = src[idx];
}

__global__ void add_k(float* __restrict__ x, const float* __restrict__ y)
{
    int idx = blockIdx.x * 256 + threadIdx.x;
    x[idx] += y[idx];
}

__global__ void zero_k(float* __restrict__ p, int n)
{
    int idx = blockIdx.x * 256 + threadIdx.x;
    if (idx < n) p[idx] = 0.f;
}

// partial column sums over token chunks; grid = B_ * (N_/128)
__global__ void colsum_k(const float* __restrict__ z, float* __restrict__ meanbuf)
{
    int b  = blockIdx.x >> 3;
    int n0 = (blockIdx.x & 7) * 128;
    int d  = threadIdx.x;
    const float* p = z + ((size_t)b * N_ + n0) * D_ + d;
    float acc = 0.f;
    #pragma unroll 8
    for (int r = 0; r < 128; r++) acc += p[(size_t)r * D_];
    atomicAdd(&meanbuf[b * D_ + d], acc);
}

// SE gate: s = sigmoid(relu(mean @ w1) @ w2); one block per batch
__global__ void gate_k(const float* __restrict__ meanbuf, const float* __restrict__ w1,
                       const float* __restrict__ w2, float* __restrict__ gatebuf)
{
    int b = blockIdx.x, tid = threadIdx.x;
    __shared__ float m[D_];
    __shared__ float t[D_ / 4];
    m[tid] = meanbuf[b * D_ + tid] * (1.f / N_);
    __syncthreads();
    if (tid < D_ / 4) {
        float acc = 0.f;
        #pragma unroll 8
        for (int d = 0; d < D_; d++) acc += m[d] * w1[d * (D_ / 4) + tid];
        t[tid] = fmaxf(acc, 0.f);
    }
    __syncthreads();
    float acc = 0.f;
    #pragma unroll 8
    for (int j = 0; j < D_ / 4; j++) acc += t[j] * w2[j * D_ + tid];
    gatebuf[b * D_ + tid] = 1.f / (1.f + expf(-acc));
}

__global__ void scale_k(float* __restrict__ x, const float* __restrict__ gate)
{
    int idx = blockIdx.x * 256 + threadIdx.x;
    int d = idx & (D_ - 1);
    int b = idx / (N_ * D_);
    x[idx] *= gate[b * D_ + d];
}

// depthwise 1x3 conv over tokens + center-tap conv + BN(eval) + exact gelu
__global__ void conv_k(const float* __restrict__ y, const float* __restrict__ wh,
                       const float* __restrict__ bh, const float* __restrict__ wv,
                       const float* __restrict__ bv, const float* __restrict__ bng,
                       const float* __restrict__ bnb, const float* __restrict__ bnm,
                       const float* __restrict__ bnv, float* __restrict__ out)
{
    int idx = blockIdx.x * 256 + threadIdx.x;
    int m = idx & (M_ - 1);
    int n = (idx / M_) & (N_ - 1);
    float y0 = y[idx];
    float ym = (n > 0)      ? y[idx - M_] : 0.f;
    float yp = (n < N_ - 1) ? y[idx + M_] : 0.f;
    float ch = wh[m * 3 + 0] * ym + wh[m * 3 + 1] * y0 + wh[m * 3 + 2] * yp + bh[m];
    float cv = wv[m * 3 + 1] * y0 + bv[m];
    float zz = ch + cv;
    zz = (zz - bnm[m]) * rsqrtf(bnv[m] + EPS_) * bng[m] + bnb[m];
    out[idx] = gelu_exact(zz);
}

// ---------------- driver -----------------------------------------------------
static void lsrc_seq(float* X, float* py, float* pmean, float* pgate,
                     const float* w1l, const float* w2l)
{
    add_k<<<(B_*N_*D_)/256, 256>>>(X, py);
    zero_k<<<(B_*D_ + 255)/256, 256>>>(pmean, B_*D_);
    colsum_k<<<B_ * (N_/128), 256>>>(X, pmean);
    gate_k<<<B_, 256>>>(pmean, w1l, w2l, pgate);
    scale_k<<<(B_*N_*D_)/256, 256>>>(X, pgate);
}

extern "C" void kernel_launch(void* const* d_in, const int* in_sizes, int n_in,
                              void* d_out, int out_size)
{
    const float* x_in  = (const float*)d_in[0];
    const float* ln1_g = (const float*)d_in[1];
    const float* ln1_b = (const float*)d_in[2];
    const float* w_qkv = (const float*)d_in[3];
    const float* w_out = (const float*)d_in[4];
    const float* b_out = (const float*)d_in[5];
    const float* ln2_g = (const float*)d_in[6];
    const float* ln2_b = (const float*)d_in[7];
    const float* w_fc1 = (const float*)d_in[8];
    const float* b_fc1 = (const float*)d_in[9];
    const float* wh    = (const float*)d_in[10];
    const float* bh    = (const float*)d_in[11];
    const float* wv    = (const float*)d_in[12];
    const float* bv    = (const float*)d_in[13];
    const float* bn_g  = (const float*)d_in[14];
    const float* bn_b  = (const float*)d_in[15];
    const float* bn_m  = (const float*)d_in[16];
    const float* bn_v  = (const float*)d_in[17];
    const float* w_fc2 = (const float*)d_in[18];
    const float* b_fc2 = (const float*)d_in[19];
    const float* ls_w1 = (const float*)d_in[20];
    const float* ls_w2 = (const float*)d_in[21];

    float *ph, *pqkv, *ps, *po, *py, *pt1, *pt2, *pmean, *pgate;
    cudaGetSymbolAddress((void**)&ph,    g_h);
    cudaGetSymbolAddress((void**)&pqkv,  g_qkv);
    cudaGetSymbolAddress((void**)&ps,    g_scores);
    cudaGetSymbolAddress((void**)&po,    g_o);
    cudaGetSymbolAddress((void**)&py,    g_y);
    cudaGetSymbolAddress((void**)&pt1,   g_t1);
    cudaGetSymbolAddress((void**)&pt2,   g_t2);
    cudaGetSymbolAddress((void**)&pmean, g_mean);
    cudaGetSymbolAddress((void**)&pgate, g_gate);

    float* X = (float*)d_out;
    const int ROWS = B_ * N_;   // 8192

    copy_k<<<(B_*N_*D_)/256, 256>>>(x_in, X);

    for (int l = 0; l < 2; l++) {
        const float* w_qkv_l = w_qkv + (size_t)l * D_ * 3 * D_;
        const float* w_out_l = w_out + (size_t)l * D_ * D_;
        const float* b_out_l = b_out + (size_t)l * D_;
        const float* w_fc1_l = w_fc1 + (size_t)l * D_ * M_;
        const float* b_fc1_l = b_fc1 + (size_t)l * M_;
        const float* w_fc2_l = w_fc2 + (size_t)l * M_ * D_;
        const float* b_fc2_l = b_fc2 + (size_t)l * D_;
        const float* w1_l    = ls_w1 + (size_t)l * D_ * (D_/4);
        const float* w2_l    = ls_w2 + (size_t)l * (D_/4) * D_;

        // --- MHSA ---
        ln_k<<<ROWS, 256>>>(X, ln1_g + l * D_, ln1_b + l * D_, ph);

        // qkv = h @ w_qkv   [8192,256]x[256,768]
        gemm3_k<128,128,64,32,false,0><<<dim3((3*D_)/128, ROWS/128, 1), 256>>>(
            ph, D_, 0, 0, w_qkv_l, 3*D_, 0, 0, pqkv, 3*D_, 0, 0,
            nullptr, D_, 1, 1.f);

        // scores = scale * q @ k^T, batched over (b,h)
        gemm3_k<128,128,64,32,true,0><<<dim3(N_/128, N_/128, B_*H_), 256>>>(
            pqkv,        3*D_, (long)N_*3*D_, DH_,
            pqkv + D_,   3*D_, (long)N_*3*D_, DH_,
            ps,          N_,   (long)H_*N_*N_, (long)N_*N_,
            nullptr, DH_, H_, 0.125f);

        softmax_k<<<B_*H_*N_, 256>>>(ps);

        // o = P @ v   [1024,1024]x[1024,64] per (b,h)
        gemm3_k<64,64,32,16,false,0><<<dim3(1, N_/64, B_*H_), 256>>>(
            ps,          N_,   (long)H_*N_*N_, (long)N_*N_,
            pqkv + 2*D_, 3*D_, (long)N_*3*D_, DH_,
            po,          D_,   (long)N_*D_,   DH_,
            nullptr, N_, H_, 1.f);

        // y = o @ w_out + b_out
        gemm3_k<128,128,64,32,false,0><<<dim3(D_/128, ROWS/128, 1), 256>>>(
            po, D_, 0, 0, w_out_l, D_, 0, 0, py, D_, 0, 0,
            b_out_l, D_, 1, 1.f);

        lsrc_seq(X, py, pmean, pgate, w1_l, w2_l);

        // --- MLP ---
        ln_k<<<ROWS, 256>>>(X, ln2_g + l * D_, ln2_b + l * D_, ph);

        // t1 = gelu(h @ w_fc1 + b_fc1)
        gemm3_k<128,128,64,32,false,1><<<dim3(M_/128, ROWS/128, 1), 256>>>(
            ph, D_, 0, 0, w_fc1_l, M_, 0, 0, pt1, M_, 0, 0,
            b_fc1_l, D_, 1, 1.f);

        // conv + BN + gelu
        conv_k<<<(B_*N_*M_)/256, 256>>>(
            pt1, wh + (size_t)l*M_*3, bh + (size_t)l*M_,
            wv + (size_t)l*M_*3, bv + (size_t)l*M_,
            bn_g + (size_t)l*M_, bn_b + (size_t)l*M_,
            bn_m + (size_t)l*M_, bn_v + (size_t)l*M_, pt2);

        // y = t2 @ w_fc2 + b_fc2
        gemm3_k<128,128,64,32,false,0><<<dim3(D_/128, ROWS/128, 1), 256>>>(
            pt2, M_, 0, 0, w_fc2_l, D_, 0, 0, py, D_, 0, 0,
            b_fc2_l, M_, 1, 1.f);

        lsrc_seq(X, py, pmean, pgate, w1_l, w2_l);
    }
}

// round 4
// speedup vs baseline: 2.5812x; 1.0321x over previous
#include <cuda_runtime.h>
#include <math.h>
#include <stdint.h>

#define B_  8
#define N_  1024
#define D_  256
#define H_  4
#define DH_ 64
#define M_  512
#define EPS_ 1e-5f

// ---------------- scratch (device globals; no allocations allowed) ----------
__device__ float g_h[B_*N_*D_];                 // LN output
__device__ float g_qkv[B_*N_*3*D_];             // qkv
__device__ float g_scores[(size_t)B_*H_*N_*N_]; // attn scores (134 MB)
__device__ float g_o[B_*N_*D_];                 // attn out
__device__ float g_y[B_*N_*D_];                 // branch output
__device__ float g_t1[B_*N_*M_];                // fc1/gelu out
__device__ float g_t2[B_*N_*M_];                // conv/bn/gelu out
__device__ float g_mean[B_*D_];
__device__ float g_gate[B_*D_];

__device__ __forceinline__ float gelu_exact(float v) {
    return 0.5f * v * (1.f + erff(v * 0.70710678118654752f));
}

__device__ __forceinline__ void mma_tf32(float& c0, float& c1, float& c2, float& c3,
                                         float a0, float a1, float a2, float a3,
                                         float b0, float b1)
{
    asm volatile(
        "mma.sync.aligned.m16n8k8.row.col.f32.tf32.tf32.f32 "
        "{%0,%1,%2,%3},{%4,%5,%6,%7},{%8,%9},{%0,%1,%2,%3};"
        : "+f"(c0), "+f"(c1), "+f"(c2), "+f"(c3)
        : "r"(__float_as_uint(a0)), "r"(__float_as_uint(a1)),
          "r"(__float_as_uint(a2)), "r"(__float_as_uint(a3)),
          "r"(__float_as_uint(b0)), "r"(__float_as_uint(b1)));
}

__device__ __forceinline__ void cp16(uint32_t dst, const void* src) {
    asm volatile("cp.async.cg.shared.global [%0], [%1], 16;" :: "r"(dst), "l"(src));
}
__device__ __forceinline__ void cp_commit() {
    asm volatile("cp.async.commit_group;" ::: "memory");
}
__device__ __forceinline__ void cp_wait0() {
    asm volatile("cp.async.wait_group 0;" ::: "memory");
}
__device__ __forceinline__ uint32_t smem_u32(const void* p) {
    return (uint32_t)__cvta_generic_to_shared(p);
}

// ---------------- batched tensor-core GEMM v4 (tf32, cp.async) ---------------
// C = alpha * A @ B(^T) (+bias) (+gelu). 2x2 warps of 64x(BN/2); BK=16,
// double-buffered cp.async. A m-major [BM][20]; B: TRANSB -> n-major [BN][20],
// else k-major [BK][BN+8]. All fragment LDS conflict-free.
template<int BM, int BN, bool TRANSB, int ACT>
__global__ __launch_bounds__(128)
void gemm4_k(const float* __restrict__ A, int lda, long sAo, long sAi,
             const float* __restrict__ Bm, int ldb, long sBo, long sBi,
             float* __restrict__ C, int ldc, long sCo, long sCi,
             const float* __restrict__ bias, int K, int Hdiv, float alpha)
{
    constexpr int BK = 16;
    constexpr int NT = 128;
    constexpr int WM = BM / 2, WN = BN / 2;
    constexpr int MT = WM / 16, NTL = WN / 8;
    constexpr int SA = BK + 4;                    // 20
    constexpr int LA = BM * BK / (4 * NT);
    constexpr int LB = BN * BK / (4 * NT);
    constexpr int BSR = TRANSB ? BN : BK;
    constexpr int BSC = TRANSB ? SA : BN + 8;

    __shared__ __align__(16) float As[2][BM][SA];
    __shared__ __align__(16) float Bs[2][BSR][BSC];

    int z  = blockIdx.z;
    int bb = z / Hdiv, hh = z % Hdiv;
    A  += (size_t)bb * sAo + (size_t)hh * sAi;
    Bm += (size_t)bb * sBo + (size_t)hh * sBi;
    C  += (size_t)bb * sCo + (size_t)hh * sCi;

    const int m0 = blockIdx.y * BM;
    const int n0 = blockIdx.x * BN;
    const int tid   = threadIdx.x;
    const int warp  = tid >> 5;
    const int lane  = tid & 31;
    const int gid   = lane >> 2;    // 0..7
    const int tig   = lane & 3;     // 0..3
    const int warpM = warp >> 1;
    const int warpN = warp & 1;

    auto issue = [&](int buf, int k0) {
        #pragma unroll
        for (int i = 0; i < LA; i++) {
            int v = tid + i * NT;
            int m = v >> 2, kq = v & 3;
            cp16(smem_u32(&As[buf][m][kq * 4]),
                 &A[(size_t)(m0 + m) * lda + k0 + kq * 4]);
        }
        #pragma unroll
        for (int i = 0; i < LB; i++) {
            int v = tid + i * NT;
            if (TRANSB) {
                int n = v >> 2, kq = v & 3;
                cp16(smem_u32(&Bs[buf][TRANSB ? n : 0][kq * 4]),
                     &Bm[(size_t)(n0 + n) * ldb + k0 + kq * 4]);
            } else {
                int nq = v & (BN / 4 - 1), k = v / (BN / 4);
                cp16(smem_u32(&Bs[buf][TRANSB ? 0 : k][nq * 4]),
                     &Bm[(size_t)(k0 + k) * ldb + n0 + nq * 4]);
            }
        }
    };

    float acc[MT][NTL][4];
    #pragma unroll
    for (int i = 0; i < MT; i++)
        #pragma unroll
        for (int j = 0; j < NTL; j++)
            #pragma unroll
            for (int c = 0; c < 4; c++) acc[i][j][c] = 0.f;

    issue(0, 0); cp_commit();
    int cur = 0;
    for (int k0 = 0; k0 < K; k0 += BK) {
        cp_wait0();
        __syncthreads();
        bool more = (k0 + BK) < K;
        if (more) { issue(cur ^ 1, k0 + BK); cp_commit(); }

        #pragma unroll
        for (int ks = 0; ks < BK; ks += 8) {
            float af[MT][4], bf[NTL][2];
            #pragma unroll
            for (int mt = 0; mt < MT; mt++) {
                int rb0 = warpM * WM + mt * 16;
                af[mt][0] = As[cur][rb0 + gid    ][ks + tig];
                af[mt][1] = As[cur][rb0 + gid + 8][ks + tig];
                af[mt][2] = As[cur][rb0 + gid    ][ks + tig + 4];
                af[mt][3] = As[cur][rb0 + gid + 8][ks + tig + 4];
            }
            #pragma unroll
            for (int nt = 0; nt < NTL; nt++) {
                int cb0 = warpN * WN + nt * 8;
                if (TRANSB) {
                    bf[nt][0] = Bs[cur][TRANSB ? (cb0 + gid) : 0][ks + tig];
                    bf[nt][1] = Bs[cur][TRANSB ? (cb0 + gid) : 0][ks + tig + 4];
                } else {
                    bf[nt][0] = Bs[cur][TRANSB ? 0 : (ks + tig)    ][cb0 + gid];
                    bf[nt][1] = Bs[cur][TRANSB ? 0 : (ks + tig + 4)][cb0 + gid];
                }
            }
            #pragma unroll
            for (int mt = 0; mt < MT; mt++)
                #pragma unroll
                for (int nt = 0; nt < NTL; nt++)
                    mma_tf32(acc[mt][nt][0], acc[mt][nt][1],
                             acc[mt][nt][2], acc[mt][nt][3],
                             af[mt][0], af[mt][1], af[mt][2], af[mt][3],
                             bf[nt][0], bf[nt][1]);
        }
        cur ^= 1;
        __syncthreads();
    }

    // epilogue: c0/c1 = (row, col), (row, col+1); c2/c3 same at row+8
    #pragma unroll
    for (int mt = 0; mt < MT; mt++) {
        int row = m0 + warpM * WM + mt * 16 + gid;
        #pragma unroll
        for (int nt = 0; nt < NTL; nt++) {
            int col = n0 + warpN * WN + nt * 8 + tig * 2;
            float v0 = acc[mt][nt][0] * alpha;
            float v1 = acc[mt][nt][1] * alpha;
            float v2 = acc[mt][nt][2] * alpha;
            float v3 = acc[mt][nt][3] * alpha;
            if (bias) {
                float b0v = bias[col], b1v = bias[col + 1];
                v0 += b0v; v1 += b1v; v2 += b0v; v3 += b1v;
            }
            if (ACT == 1) {
                v0 = gelu_exact(v0); v1 = gelu_exact(v1);
                v2 = gelu_exact(v2); v3 = gelu_exact(v3);
            }
            *(float2*)&C[(size_t)row * ldc + col]       = make_float2(v0, v1);
            *(float2*)&C[(size_t)(row + 8) * ldc + col] = make_float2(v2, v3);
        }
    }
}

// ---------------- fused copy + layernorm (layer 0 entry) --------------------
__global__ void copy_ln_k(const float* __restrict__ xin, float* __restrict__ X,
                          const float* __restrict__ g, const float* __restrict__ b,
                          float* __restrict__ out)
{
    int row = blockIdx.x, tid = threadIdx.x;
    __shared__ float s[256];
    float v = xin[(size_t)row * D_ + tid];
    X[(size_t)row * D_ + tid] = v;
    s[tid] = v; __syncthreads();
    for (int st = 128; st > 0; st >>= 1) { if (tid < st) s[tid] += s[tid + st]; __syncthreads(); }
    float mu = s[0] * (1.f / D_);
    __syncthreads();
    float d = v - mu;
    s[tid] = d * d; __syncthreads();
    for (int st = 128; st > 0; st >>= 1) { if (tid < st) s[tid] += s[tid + st]; __syncthreads(); }
    float var = s[0] * (1.f / D_);
    out[(size_t)row * D_ + tid] = d * rsqrtf(var + EPS_) * g[tid] + b[tid];
}

// ---------------- fused scale + layernorm -----------------------------------
__global__ void scale_ln_k(float* __restrict__ X, const float* __restrict__ gate,
                           const float* __restrict__ g, const float* __restrict__ b,
                           float* __restrict__ out)
{
    int row = blockIdx.x, tid = threadIdx.x;
    int bb = row >> 10;
    __shared__ float s[256];
    float v = X[(size_t)row * D_ + tid] * gate[bb * D_ + tid];
    X[(size_t)row * D_ + tid] = v;
    s[tid] = v; __syncthreads();
    for (int st = 128; st > 0; st >>= 1) { if (tid < st) s[tid] += s[tid + st]; __syncthreads(); }
    float mu = s[0] * (1.f / D_);
    __syncthreads();
    float d = v - mu;
    s[tid] = d * d; __syncthreads();
    for (int st = 128; st > 0; st >>= 1) { if (tid < st) s[tid] += s[tid + st]; __syncthreads(); }
    float var = s[0] * (1.f / D_);
    out[(size_t)row * D_ + tid] = d * rsqrtf(var + EPS_) * g[tid] + b[tid];
}

// ---------------- row softmax over width 1024 -------------------------------
__global__ void softmax_k(float* __restrict__ S)
{
    size_t row = blockIdx.x;
    float* p = S + row * N_;
    int tid = threadIdx.x;
    __shared__ float s[256];
    float v[4];
    float mx = -3.4e38f;
    #pragma unroll
    for (int i = 0; i < 4; i++) { v[i] = p[tid + i * 256]; mx = fmaxf(mx, v[i]); }
    s[tid] = mx; __syncthreads();
    for (int st = 128; st > 0; st >>= 1) { if (tid < st) s[tid] = fmaxf(s[tid], s[tid + st]); __syncthreads(); }
    mx = s[0]; __syncthreads();
    float sum = 0.f;
    #pragma unroll
    for (int i = 0; i < 4; i++) { v[i] = expf(v[i] - mx); sum += v[i]; }
    s[tid] = sum; __syncthreads();
    for (int st = 128; st > 0; st >>= 1) { if (tid < st) s[tid] += s[tid + st]; __syncthreads(); }
    float inv = 1.f / s[0];
    #pragma unroll
    for (int i = 0; i < 4; i++) p[tid + i * 256] = v[i] * inv;
}

// ---------------- residual add fused with column-sum ------------------------
__global__ void add_colsum_k(float* __restrict__ X, const float* __restrict__ y,
                             float* __restrict__ meanbuf)
{
    int b  = blockIdx.x >> 3;
    int n0 = (blockIdx.x & 7) * 128;
    int d  = threadIdx.x;
    size_t base = ((size_t)b * N_ + n0) * D_ + d;
    float acc = 0.f;
    #pragma unroll 8
    for (int r = 0; r < 128; r++) {
        size_t idx = base + (size_t)r * D_;
        float v = X[idx] + y[idx];
        X[idx] = v;
        acc += v;
    }
    atomicAdd(&meanbuf[b * D_ + d], acc);
}

__global__ void zero_k(float* __restrict__ p, int n)
{
    int idx = blockIdx.x * 256 + threadIdx.x;
    if (idx < n) p[idx] = 0.f;
}

// SE gate: s = sigmoid(relu(mean @ w1) @ w2); one block per batch
__global__ void gate_k(const float* __restrict__ meanbuf, const float* __restrict__ w1,
                       const float* __restrict__ w2, float* __restrict__ gatebuf)
{
    int b = blockIdx.x, tid = threadIdx.x;
    __shared__ float m[D_];
    __shared__ float t[D_ / 4];
    m[tid] = meanbuf[b * D_ + tid] * (1.f / N_);
    __syncthreads();
    if (tid < D_ / 4) {
        float acc = 0.f;
        #pragma unroll 8
        for (int d = 0; d < D_; d++) acc += m[d] * w1[d * (D_ / 4) + tid];
        t[tid] = fmaxf(acc, 0.f);
    }
    __syncthreads();
    float acc = 0.f;
    #pragma unroll 8
    for (int j = 0; j < D_ / 4; j++) acc += t[j] * w2[j * D_ + tid];
    gatebuf[b * D_ + tid] = 1.f / (1.f + expf(-acc));
}

__global__ void scale_k(float* __restrict__ x, const float* __restrict__ gate)
{
    int idx = blockIdx.x * 256 + threadIdx.x;
    int d = idx & (D_ - 1);
    int b = idx / (N_ * D_);
    x[idx] *= gate[b * D_ + d];
}

// depthwise 1x3 conv over tokens + center-tap conv + BN(eval) + exact gelu
__global__ void conv_k(const float* __restrict__ y, const float* __restrict__ wh,
                       const float* __restrict__ bh, const float* __restrict__ wv,
                       const float* __restrict__ bv, const float* __restrict__ bng,
                       const float* __restrict__ bnb, const float* __restrict__ bnm,
                       const float* __restrict__ bnv, float* __restrict__ out)
{
    int idx = blockIdx.x * 256 + threadIdx.x;
    int m = idx & (M_ - 1);
    int n = (idx / M_) & (N_ - 1);
    float y0 = y[idx];
    float ym = (n > 0)      ? y[idx - M_] : 0.f;
    float yp = (n < N_ - 1) ? y[idx + M_] : 0.f;
    float ch = wh[m * 3 + 0] * ym + wh[m * 3 + 1] * y0 + wh[m * 3 + 2] * yp + bh[m];
    float cv = wv[m * 3 + 1] * y0 + bv[m];
    float zz = ch + cv;
    zz = (zz - bnm[m]) * rsqrtf(bnv[m] + EPS_) * bng[m] + bnb[m];
    out[idx] = gelu_exact(zz);
}

// ---------------- driver -----------------------------------------------------
extern "C" void kernel_launch(void* const* d_in, const int* in_sizes, int n_in,
                              void* d_out, int out_size)
{
    const float* x_in  = (const float*)d_in[0];
    const float* ln1_g = (const float*)d_in[1];
    const float* ln1_b = (const float*)d_in[2];
    const float* w_qkv = (const float*)d_in[3];
    const float* w_out = (const float*)d_in[4];
    const float* b_out = (const float*)d_in[5];
    const float* ln2_g = (const float*)d_in[6];
    const float* ln2_b = (const float*)d_in[7];
    const float* w_fc1 = (const float*)d_in[8];
    const float* b_fc1 = (const float*)d_in[9];
    const float* wh    = (const float*)d_in[10];
    const float* bh    = (const float*)d_in[11];
    const float* wv    = (const float*)d_in[12];
    const float* bv    = (const float*)d_in[13];
    const float* bn_g  = (const float*)d_in[14];
    const float* bn_b  = (const float*)d_in[15];
    const float* bn_m  = (const float*)d_in[16];
    const float* bn_v  = (const float*)d_in[17];
    const float* w_fc2 = (const float*)d_in[18];
    const float* b_fc2 = (const float*)d_in[19];
    const float* ls_w1 = (const float*)d_in[20];
    const float* ls_w2 = (const float*)d_in[21];

    float *ph, *pqkv, *ps, *po, *py, *pt1, *pt2, *pmean, *pgate;
    cudaGetSymbolAddress((void**)&ph,    g_h);
    cudaGetSymbolAddress((void**)&pqkv,  g_qkv);
    cudaGetSymbolAddress((void**)&ps,    g_scores);
    cudaGetSymbolAddress((void**)&po,    g_o);
    cudaGetSymbolAddress((void**)&py,    g_y);
    cudaGetSymbolAddress((void**)&pt1,   g_t1);
    cudaGetSymbolAddress((void**)&pt2,   g_t2);
    cudaGetSymbolAddress((void**)&pmean, g_mean);
    cudaGetSymbolAddress((void**)&pgate, g_gate);

    float* X = (float*)d_out;
    const int ROWS = B_ * N_;   // 8192

    for (int l = 0; l < 2; l++) {
        const float* w_qkv_l = w_qkv + (size_t)l * D_ * 3 * D_;
        const float* w_out_l = w_out + (size_t)l * D_ * D_;
        const float* b_out_l = b_out + (size_t)l * D_;
        const float* w_fc1_l = w_fc1 + (size_t)l * D_ * M_;
        const float* b_fc1_l = b_fc1 + (size_t)l * M_;
        const float* w_fc2_l = w_fc2 + (size_t)l * M_ * D_;
        const float* b_fc2_l = b_fc2 + (size_t)l * D_;
        const float* w1_l    = ls_w1 + (size_t)l * D_ * (D_/4);
        const float* w2_l    = ls_w2 + (size_t)l * (D_/4) * D_;

        // --- MHSA ---  (h = LN1(X); layer 0 fuses the initial copy)
        if (l == 0)
            copy_ln_k<<<ROWS, 256>>>(x_in, X, ln1_g, ln1_b, ph);
        // for l>0, h was produced by the fused scale_ln at end of prev layer

        // qkv = h @ w_qkv   [8192,256]x[256,768]
        gemm4_k<128,128,false,0><<<dim3((3*D_)/128, ROWS/128, 1), 128>>>(
            ph, D_, 0, 0, w_qkv_l, 3*D_, 0, 0, pqkv, 3*D_, 0, 0,
            nullptr, D_, 1, 1.f);

        // scores = scale * q @ k^T, batched over (b,h)
        gemm4_k<128,128,true,0><<<dim3(N_/128, N_/128, B_*H_), 128>>>(
            pqkv,        3*D_, (long)N_*3*D_, DH_,
            pqkv + D_,   3*D_, (long)N_*3*D_, DH_,
            ps,          N_,   (long)H_*N_*N_, (long)N_*N_,
            nullptr, DH_, H_, 0.125f);

        softmax_k<<<B_*H_*N_, 256>>>(ps);

        // o = P @ v   [1024,1024]x[1024,64] per (b,h)
        gemm4_k<128,64,false,0><<<dim3(1, N_/128, B_*H_), 128>>>(
            ps,          N_,   (long)H_*N_*N_, (long)N_*N_,
            pqkv + 2*D_, 3*D_, (long)N_*3*D_, DH_,
            po,          D_,   (long)N_*D_,   DH_,
            nullptr, N_, H_, 1.f);

        // y = o @ w_out + b_out
        gemm4_k<128,128,false,0><<<dim3(D_/128, ROWS/128, 1), 128>>>(
            po, D_, 0, 0, w_out_l, D_, 0, 0, py, D_, 0, 0,
            b_out_l, D_, 1, 1.f);

        // lsrc #1 (fused): X += y, colsum, gate, then scale fused with LN2
        zero_k<<<(B_*D_ + 255)/256, 256>>>(pmean, B_*D_);
        add_colsum_k<<<B_ * (N_/128), 256>>>(X, py, pmean);
        gate_k<<<B_, 256>>>(pmean, w1_l, w2_l, pgate);
        scale_ln_k<<<ROWS, 256>>>(X, pgate, ln2_g + l * D_, ln2_b + l * D_, ph);

        // --- MLP ---
        // t1 = gelu(h @ w_fc1 + b_fc1)
        gemm4_k<128,128,false,1><<<dim3(M_/128, ROWS/128, 1), 128>>>(
            ph, D_, 0, 0, w_fc1_l, M_, 0, 0, pt1, M_, 0, 0,
            b_fc1_l, D_, 1, 1.f);

        // conv + BN + gelu
        conv_k<<<(B_*N_*M_)/256, 256>>>(
            pt1, wh + (size_t)l*M_*3, bh + (size_t)l*M_,
            wv + (size_t)l*M_*3, bv + (size_t)l*M_,
            bn_g + (size_t)l*M_, bn_b + (size_t)l*M_,
            bn_m + (size_t)l*M_, bn_v + (size_t)l*M_, pt2);

        // y = t2 @ w_fc2 + b_fc2
        gemm4_k<128,128,false,0><<<dim3(D_/128, ROWS/128, 1), 128>>>(
            pt2, M_, 0, 0, w_fc2_l, D_, 0, 0, py, D_, 0, 0,
            b_fc2_l, M_, 1, 1.f);

        // lsrc #2 (fused); last one has no following LN
        zero_k<<<(B_*D_ + 255)/256, 256>>>(pmean, B_*D_);
        add_colsum_k<<<B_ * (N_/128), 256>>>(X, py, pmean);
        gate_k<<<B_, 256>>>(pmean, w1_l, w2_l, pgate);
        if (l + 1 < 2)
            scale_ln_k<<<ROWS, 256>>>(X, pgate, ln1_g + (l+1) * D_, ln1_b + (l+1) * D_, ph);
        else
            scale_k<<<(B_*N_*D_)/256, 256>>>(X, pgate);
    }
}

// round 5
// speedup vs baseline: 3.4902x; 1.3522x over previous
#include <cuda_runtime.h>
#include <math.h>
#include <stdint.h>

#define B_  8
#define N_  1024
#define D_  256
#define H_  4
#define DH_ 64
#define M_  512
#define EPS_ 1e-5f

// ---------------- scratch (device globals; no allocations allowed) ----------
__device__ float g_h[B_*N_*D_];                 // LN output
__device__ float g_qkv[B_*N_*3*D_];             // qkv
__device__ float g_o[B_*N_*D_];                 // attn out
__device__ float g_y[B_*N_*D_];                 // branch output
__device__ float g_t1[B_*N_*M_];                // fc1/gelu out
__device__ float g_t2[B_*N_*M_];                // conv/bn/gelu out
__device__ float g_mean[B_*D_];
__device__ float g_gate[B_*D_];

__device__ __forceinline__ float gelu_exact(float v) {
    return 0.5f * v * (1.f + erff(v * 0.70710678118654752f));
}

__device__ __forceinline__ void mma_tf32(float& c0, float& c1, float& c2, float& c3,
                                         float a0, float a1, float a2, float a3,
                                         float b0, float b1)
{
    asm volatile(
        "mma.sync.aligned.m16n8k8.row.col.f32.tf32.tf32.f32 "
        "{%0,%1,%2,%3},{%4,%5,%6,%7},{%8,%9},{%0,%1,%2,%3};"
        : "+f"(c0), "+f"(c1), "+f"(c2), "+f"(c3)
        : "r"(__float_as_uint(a0)), "r"(__float_as_uint(a1)),
          "r"(__float_as_uint(a2)), "r"(__float_as_uint(a3)),
          "r"(__float_as_uint(b0)), "r"(__float_as_uint(b1)));
}

__device__ __forceinline__ void cp16(uint32_t dst, const void* src) {
    asm volatile("cp.async.cg.shared.global [%0], [%1], 16;" :: "r"(dst), "l"(src));
}
__device__ __forceinline__ void cp_commit() {
    asm volatile("cp.async.commit_group;" ::: "memory");
}
__device__ __forceinline__ void cp_wait0() {
    asm volatile("cp.async.wait_group 0;" ::: "memory");
}
__device__ __forceinline__ uint32_t smem_u32(const void* p) {
    return (uint32_t)__cvta_generic_to_shared(p);
}

// ---------------- flash attention --------------------------------------------
// One CTA = 64 query rows of one (b,h). 4 warps x 16 rows. Iterates 16 KV
// tiles of 64, K/V double-buffered via cp.async. Online softmax in registers.
#define FBM 64
#define FBN 64

struct FlashSmem {
    float Q[FBM][68];        // q rows (pre-scaled), m-major
    float K[2][FBN][68];     // kv-major [kv][d]
    float V[2][FBN][72];     // k-major  [kv][d]
    float P[4][16][68];      // per-warp probs staging
};
#define FLASH_SMEM_BYTES ((int)sizeof(FlashSmem))

__global__ __launch_bounds__(128)
void flash_k(const float* __restrict__ qkv, float* __restrict__ Og)
{
    extern __shared__ float smem_raw[];
    FlashSmem& S = *(FlashSmem*)smem_raw;

    const int bh = blockIdx.z;
    const int b = bh >> 2, h = bh & 3;
    const int m0 = blockIdx.y * FBM;
    const int tid  = threadIdx.x;
    const int warp = tid >> 5, lane = tid & 31;
    const int gid  = lane >> 2, tig = lane & 3;

    const float* qb = qkv + ((size_t)b * N_) * (3*D_) + h * DH_;

    // load Q tile once, scaled by DH^-0.5
    #pragma unroll
    for (int i = 0; i < 8; i++) {
        int v = tid + i * 128;
        int r = v >> 4, dq = v & 15;
        float4 t = *(const float4*)&qb[(size_t)(m0 + r) * (3*D_) + dq * 4];
        t.x *= 0.125f; t.y *= 0.125f; t.z *= 0.125f; t.w *= 0.125f;
        *(float4*)&S.Q[r][dq * 4] = t;
    }

    auto issue = [&](int buf, int t) {
        int n0 = t * FBN;
        const float* kb = qkv + ((size_t)b * N_ + n0) * (3*D_) + D_ + h * DH_;
        const float* vb = kb + D_;
        #pragma unroll
        for (int i = 0; i < 8; i++) {
            int v = tid + i * 128;
            int r = v >> 4, dq = v & 15;
            cp16(smem_u32(&S.K[buf][r][dq * 4]), &kb[(size_t)r * (3*D_) + dq * 4]);
            cp16(smem_u32(&S.V[buf][r][dq * 4]), &vb[(size_t)r * (3*D_) + dq * 4]);
        }
    };

    float mr0 = -1e30f, mr1 = -1e30f, l0 = 0.f, l1 = 0.f;
    float o[8][4];
    #pragma unroll
    for (int nt = 0; nt < 8; nt++)
        #pragma unroll
        for (int c = 0; c < 4; c++) o[nt][c] = 0.f;

    const int qrow = warp * 16 + gid;

    issue(0, 0); cp_commit();
    for (int t = 0; t < N_ / FBN; t++) {
        int cur = t & 1;
        cp_wait0();
        __syncthreads();             // tile t visible; all warps done with t-1
        if (t + 1 < N_ / FBN) { issue(cur ^ 1, t + 1); cp_commit(); }

        // ---- S = Qs @ K^T ----
        float s[8][4];
        #pragma unroll
        for (int nt = 0; nt < 8; nt++)
            #pragma unroll
            for (int c = 0; c < 4; c++) s[nt][c] = 0.f;

        #pragma unroll
        for (int ks = 0; ks < DH_; ks += 8) {
            float a0 = S.Q[qrow    ][ks + tig];
            float a1 = S.Q[qrow + 8][ks + tig];
            float a2 = S.Q[qrow    ][ks + tig + 4];
            float a3 = S.Q[qrow + 8][ks + tig + 4];
            #pragma unroll
            for (int nt = 0; nt < 8; nt++) {
                float b0 = S.K[cur][nt * 8 + gid][ks + tig];
                float b1 = S.K[cur][nt * 8 + gid][ks + tig + 4];
                mma_tf32(s[nt][0], s[nt][1], s[nt][2], s[nt][3],
                         a0, a1, a2, a3, b0, b1);
            }
        }

        // ---- online softmax update ----
        float rm0 = -1e30f, rm1 = -1e30f;
        #pragma unroll
        for (int nt = 0; nt < 8; nt++) {
            rm0 = fmaxf(rm0, fmaxf(s[nt][0], s[nt][1]));
            rm1 = fmaxf(rm1, fmaxf(s[nt][2], s[nt][3]));
        }
        rm0 = fmaxf(rm0, __shfl_xor_sync(0xffffffff, rm0, 1));
        rm0 = fmaxf(rm0, __shfl_xor_sync(0xffffffff, rm0, 2));
        rm1 = fmaxf(rm1, __shfl_xor_sync(0xffffffff, rm1, 1));
        rm1 = fmaxf(rm1, __shfl_xor_sync(0xffffffff, rm1, 2));

        float mn0 = fmaxf(mr0, rm0), mn1 = fmaxf(mr1, rm1);
        float sc0 = __expf(mr0 - mn0), sc1 = __expf(mr1 - mn1);
        mr0 = mn0; mr1 = mn1;

        float rs0 = 0.f, rs1 = 0.f;
        #pragma unroll
        for (int nt = 0; nt < 8; nt++) {
            s[nt][0] = __expf(s[nt][0] - mn0);
            s[nt][1] = __expf(s[nt][1] - mn0);
            s[nt][2] = __expf(s[nt][2] - mn1);
            s[nt][3] = __expf(s[nt][3] - mn1);
            rs0 += s[nt][0] + s[nt][1];
            rs1 += s[nt][2] + s[nt][3];
        }
        rs0 += __shfl_xor_sync(0xffffffff, rs0, 1);
        rs0 += __shfl_xor_sync(0xffffffff, rs0, 2);
        rs1 += __shfl_xor_sync(0xffffffff, rs1, 1);
        rs1 += __shfl_xor_sync(0xffffffff, rs1, 2);
        l0 = l0 * sc0 + rs0;
        l1 = l1 * sc1 + rs1;

        #pragma unroll
        for (int nt = 0; nt < 8; nt++) {
            o[nt][0] *= sc0; o[nt][1] *= sc0;
            o[nt][2] *= sc1; o[nt][3] *= sc1;
        }

        // ---- stage P in warp-private smem ----
        #pragma unroll
        for (int nt = 0; nt < 8; nt++) {
            S.P[warp][gid    ][nt * 8 + tig * 2    ] = s[nt][0];
            S.P[warp][gid    ][nt * 8 + tig * 2 + 1] = s[nt][1];
            S.P[warp][gid + 8][nt * 8 + tig * 2    ] = s[nt][2];
            S.P[warp][gid + 8][nt * 8 + tig * 2 + 1] = s[nt][3];
        }
        __syncwarp();

        // ---- O += P @ V ----
        #pragma unroll
        for (int ks = 0; ks < FBN; ks += 8) {
            float a0 = S.P[warp][gid    ][ks + tig];
            float a1 = S.P[warp][gid + 8][ks + tig];
            float a2 = S.P[warp][gid    ][ks + tig + 4];
            float a3 = S.P[warp][gid + 8][ks + tig + 4];
            #pragma unroll
            for (int nt = 0; nt < 8; nt++) {
                float b0 = S.V[cur][ks + tig    ][nt * 8 + gid];
                float b1 = S.V[cur][ks + tig + 4][nt * 8 + gid];
                mma_tf32(o[nt][0], o[nt][1], o[nt][2], o[nt][3],
                         a0, a1, a2, a3, b0, b1);
            }
        }
        __syncwarp();
    }

    // ---- epilogue ----
    float inv0 = 1.f / l0, inv1 = 1.f / l1;
    int r0 = m0 + qrow;
    float* ob0 = Og + ((size_t)b * N_ + r0    ) * D_ + h * DH_;
    float* ob1 = Og + ((size_t)b * N_ + r0 + 8) * D_ + h * DH_;
    #pragma unroll
    for (int nt = 0; nt < 8; nt++) {
        int col = nt * 8 + tig * 2;
        *(float2*)&ob0[col] = make_float2(o[nt][0] * inv0, o[nt][1] * inv0);
        *(float2*)&ob1[col] = make_float2(o[nt][2] * inv1, o[nt][3] * inv1);
    }
}

// ---------------- batched tensor-core GEMM v4 (tf32, cp.async) ---------------
template<int BM, int BN, bool TRANSB, int ACT>
__global__ __launch_bounds__(128)
void gemm4_k(const float* __restrict__ A, int lda, long sAo, long sAi,
             const float* __restrict__ Bm, int ldb, long sBo, long sBi,
             float* __restrict__ C, int ldc, long sCo, long sCi,
             const float* __restrict__ bias, int K, int Hdiv, float alpha)
{
    constexpr int BK = 16;
    constexpr int NT = 128;
    constexpr int WM = BM / 2, WN = BN / 2;
    constexpr int MT = WM / 16, NTL = WN / 8;
    constexpr int SA = BK + 4;
    constexpr int LA = BM * BK / (4 * NT);
    constexpr int LB = BN * BK / (4 * NT);
    constexpr int BSR = TRANSB ? BN : BK;
    constexpr int BSC = TRANSB ? SA : BN + 8;

    __shared__ __align__(16) float As[2][BM][SA];
    __shared__ __align__(16) float Bs[2][BSR][BSC];

    int z  = blockIdx.z;
    int bb = z / Hdiv, hh = z % Hdiv;
    A  += (size_t)bb * sAo + (size_t)hh * sAi;
    Bm += (size_t)bb * sBo + (size_t)hh * sBi;
    C  += (size_t)bb * sCo + (size_t)hh * sCi;

    const int m0 = blockIdx.y * BM;
    const int n0 = blockIdx.x * BN;
    const int tid   = threadIdx.x;
    const int warp  = tid >> 5;
    const int lane  = tid & 31;
    const int gid   = lane >> 2;
    const int tig   = lane & 3;
    const int warpM = warp >> 1;
    const int warpN = warp & 1;

    auto issue = [&](int buf, int k0) {
        #pragma unroll
        for (int i = 0; i < LA; i++) {
            int v = tid + i * NT;
            int m = v >> 2, kq = v & 3;
            cp16(smem_u32(&As[buf][m][kq * 4]),
                 &A[(size_t)(m0 + m) * lda + k0 + kq * 4]);
        }
        #pragma unroll
        for (int i = 0; i < LB; i++) {
            int v = tid + i * NT;
            if (TRANSB) {
                int n = v >> 2, kq = v & 3;
                cp16(smem_u32(&Bs[buf][TRANSB ? n : 0][kq * 4]),
                     &Bm[(size_t)(n0 + n) * ldb + k0 + kq * 4]);
            } else {
                int nq = v & (BN / 4 - 1), k = v / (BN / 4);
                cp16(smem_u32(&Bs[buf][TRANSB ? 0 : k][nq * 4]),
                     &Bm[(size_t)(k0 + k) * ldb + n0 + nq * 4]);
            }
        }
    };

    float acc[MT][NTL][4];
    #pragma unroll
    for (int i = 0; i < MT; i++)
        #pragma unroll
        for (int j = 0; j < NTL; j++)
            #pragma unroll
            for (int c = 0; c < 4; c++) acc[i][j][c] = 0.f;

    issue(0, 0); cp_commit();
    int cur = 0;
    for (int k0 = 0; k0 < K; k0 += BK) {
        cp_wait0();
        __syncthreads();
        bool more = (k0 + BK) < K;
        if (more) { issue(cur ^ 1, k0 + BK); cp_commit(); }

        #pragma unroll
        for (int ks = 0; ks < BK; ks += 8) {
            float af[MT][4], bf[NTL][2];
            #pragma unroll
            for (int mt = 0; mt < MT; mt++) {
                int rb0 = warpM * WM + mt * 16;
                af[mt][0] = As[cur][rb0 + gid    ][ks + tig];
                af[mt][1] = As[cur][rb0 + gid + 8][ks + tig];
                af[mt][2] = As[cur][rb0 + gid    ][ks + tig + 4];
                af[mt][3] = As[cur][rb0 + gid + 8][ks + tig + 4];
            }
            #pragma unroll
            for (int nt = 0; nt < NTL; nt++) {
                int cb0 = warpN * WN + nt * 8;
                if (TRANSB) {
                    bf[nt][0] = Bs[cur][TRANSB ? (cb0 + gid) : 0][ks + tig];
                    bf[nt][1] = Bs[cur][TRANSB ? (cb0 + gid) : 0][ks + tig + 4];
                } else {
                    bf[nt][0] = Bs[cur][TRANSB ? 0 : (ks + tig)    ][cb0 + gid];
                    bf[nt][1] = Bs[cur][TRANSB ? 0 : (ks + tig + 4)][cb0 + gid];
                }
            }
            #pragma unroll
            for (int mt = 0; mt < MT; mt++)
                #pragma unroll
                for (int nt = 0; nt < NTL; nt++)
                    mma_tf32(acc[mt][nt][0], acc[mt][nt][1],
                             acc[mt][nt][2], acc[mt][nt][3],
                             af[mt][0], af[mt][1], af[mt][2], af[mt][3],
                             bf[nt][0], bf[nt][1]);
        }
        cur ^= 1;
        __syncthreads();
    }

    #pragma unroll
    for (int mt = 0; mt < MT; mt++) {
        int row = m0 + warpM * WM + mt * 16 + gid;
        #pragma unroll
        for (int nt = 0; nt < NTL; nt++) {
            int col = n0 + warpN * WN + nt * 8 + tig * 2;
            float v0 = acc[mt][nt][0] * alpha;
            float v1 = acc[mt][nt][1] * alpha;
            float v2 = acc[mt][nt][2] * alpha;
            float v3 = acc[mt][nt][3] * alpha;
            if (bias) {
                float b0v = bias[col], b1v = bias[col + 1];
                v0 += b0v; v1 += b1v; v2 += b0v; v3 += b1v;
            }
            if (ACT == 1) {
                v0 = gelu_exact(v0); v1 = gelu_exact(v1);
                v2 = gelu_exact(v2); v3 = gelu_exact(v3);
            }
            *(float2*)&C[(size_t)row * ldc + col]       = make_float2(v0, v1);
            *(float2*)&C[(size_t)(row + 8) * ldc + col] = make_float2(v2, v3);
        }
    }
}

// ---------------- fused copy + layernorm (layer 0 entry) --------------------
__global__ void copy_ln_k(const float* __restrict__ xin, float* __restrict__ X,
                          const float* __restrict__ g, const float* __restrict__ b,
                          float* __restrict__ out)
{
    int row = blockIdx.x, tid = threadIdx.x;
    __shared__ float s[256];
    float v = xin[(size_t)row * D_ + tid];
    X[(size_t)row * D_ + tid] = v;
    s[tid] = v; __syncthreads();
    for (int st = 128; st > 0; st >>= 1) { if (tid < st) s[tid] += s[tid + st]; __syncthreads(); }
    float mu = s[0] * (1.f / D_);
    __syncthreads();
    float d = v - mu;
    s[tid] = d * d; __syncthreads();
    for (int st = 128; st > 0; st >>= 1) { if (tid < st) s[tid] += s[tid + st]; __syncthreads(); }
    float var = s[0] * (1.f / D_);
    out[(size_t)row * D_ + tid] = d * rsqrtf(var + EPS_) * g[tid] + b[tid];
}

// ---------------- fused scale + layernorm -----------------------------------
__global__ void scale_ln_k(float* __restrict__ X, const float* __restrict__ gate,
                           const float* __restrict__ g, const float* __restrict__ b,
                           float* __restrict__ out)
{
    int row = blockIdx.x, tid = threadIdx.x;
    int bb = row >> 10;
    __shared__ float s[256];
    float v = X[(size_t)row * D_ + tid] * gate[bb * D_ + tid];
    X[(size_t)row * D_ + tid] = v;
    s[tid] = v; __syncthreads();
    for (int st = 128; st > 0; st >>= 1) { if (tid < st) s[tid] += s[tid + st]; __syncthreads(); }
    float mu = s[0] * (1.f / D_);
    __syncthreads();
    float d = v - mu;
    s[tid] = d * d; __syncthreads();
    for (int st = 128; st > 0; st >>= 1) { if (tid < st) s[tid] += s[tid + st]; __syncthreads(); }
    float var = s[0] * (1.f / D_);
    out[(size_t)row * D_ + tid] = d * rsqrtf(var + EPS_) * g[tid] + b[tid];
}

// ---------------- residual add fused with column-sum ------------------------
__global__ void add_colsum_k(float* __restrict__ X, const float* __restrict__ y,
                             float* __restrict__ meanbuf)
{
    int b  = blockIdx.x >> 3;
    int n0 = (blockIdx.x & 7) * 128;
    int d  = threadIdx.x;
    size_t base = ((size_t)b * N_ + n0) * D_ + d;
    float acc = 0.f;
    #pragma unroll 8
    for (int r = 0; r < 128; r++) {
        size_t idx = base + (size_t)r * D_;
        float v = X[idx] + y[idx];
        X[idx] = v;
        acc += v;
    }
    atomicAdd(&meanbuf[b * D_ + d], acc);
}

__global__ void zero_k(float* __restrict__ p, int n)
{
    int idx = blockIdx.x * 256 + threadIdx.x;
    if (idx < n) p[idx] = 0.f;
}

// SE gate: s = sigmoid(relu(mean @ w1) @ w2); one block per batch
__global__ void gate_k(const float* __restrict__ meanbuf, const float* __restrict__ w1,
                       const float* __restrict__ w2, float* __restrict__ gatebuf)
{
    int b = blockIdx.x, tid = threadIdx.x;
    __shared__ float m[D_];
    __shared__ float t[D_ / 4];
    m[tid] = meanbuf[b * D_ + tid] * (1.f / N_);
    __syncthreads();
    if (tid < D_ / 4) {
        float acc = 0.f;
        #pragma unroll 8
        for (int d = 0; d < D_; d++) acc += m[d] * w1[d * (D_ / 4) + tid];
        t[tid] = fmaxf(acc, 0.f);
    }
    __syncthreads();
    float acc = 0.f;
    #pragma unroll 8
    for (int j = 0; j < D_ / 4; j++) acc += t[j] * w2[j * D_ + tid];
    gatebuf[b * D_ + tid] = 1.f / (1.f + expf(-acc));
}

__global__ void scale_k(float* __restrict__ x, const float* __restrict__ gate)
{
    int idx = blockIdx.x * 256 + threadIdx.x;
    int d = idx & (D_ - 1);
    int b = idx / (N_ * D_);
    x[idx] *= gate[b * D_ + d];
}

// depthwise 1x3 conv over tokens + center-tap conv + BN(eval) + exact gelu
__global__ void conv_k(const float* __restrict__ y, const float* __restrict__ wh,
                       const float* __restrict__ bh, const float* __restrict__ wv,
                       const float* __restrict__ bv, const float* __restrict__ bng,
                       const float* __restrict__ bnb, const float* __restrict__ bnm,
                       const float* __restrict__ bnv, float* __restrict__ out)
{
    int idx = blockIdx.x * 256 + threadIdx.x;
    int m = idx & (M_ - 1);
    int n = (idx / M_) & (N_ - 1);
    float y0 = y[idx];
    float ym = (n > 0)      ? y[idx - M_] : 0.f;
    float yp = (n < N_ - 1) ? y[idx + M_] : 0.f;
    float ch = wh[m * 3 + 0] * ym + wh[m * 3 + 1] * y0 + wh[m * 3 + 2] * yp + bh[m];
    float cv = wv[m * 3 + 1] * y0 + bv[m];
    float zz = ch + cv;
    zz = (zz - bnm[m]) * rsqrtf(bnv[m] + EPS_) * bng[m] + bnb[m];
    out[idx] = gelu_exact(zz);
}

// ---------------- driver -----------------------------------------------------
extern "C" void kernel_launch(void* const* d_in, const int* in_sizes, int n_in,
                              void* d_out, int out_size)
{
    const float* x_in  = (const float*)d_in[0];
    const float* ln1_g = (const float*)d_in[1];
    const float* ln1_b = (const float*)d_in[2];
    const float* w_qkv = (const float*)d_in[3];
    const float* w_out = (const float*)d_in[4];
    const float* b_out = (const float*)d_in[5];
    const float* ln2_g = (const float*)d_in[6];
    const float* ln2_b = (const float*)d_in[7];
    const float* w_fc1 = (const float*)d_in[8];
    const float* b_fc1 = (const float*)d_in[9];
    const float* wh    = (const float*)d_in[10];
    const float* bh    = (const float*)d_in[11];
    const float* wv    = (const float*)d_in[12];
    const float* bv    = (const float*)d_in[13];
    const float* bn_g  = (const float*)d_in[14];
    const float* bn_b  = (const float*)d_in[15];
    const float* bn_m  = (const float*)d_in[16];
    const float* bn_v  = (const float*)d_in[17];
    const float* w_fc2 = (const float*)d_in[18];
    const float* b_fc2 = (const float*)d_in[19];
    const float* ls_w1 = (const float*)d_in[20];
    const float* ls_w2 = (const float*)d_in[21];

    float *ph, *pqkv, *po, *py, *pt1, *pt2, *pmean, *pgate;
    cudaGetSymbolAddress((void**)&ph,    g_h);
    cudaGetSymbolAddress((void**)&pqkv,  g_qkv);
    cudaGetSymbolAddress((void**)&po,    g_o);
    cudaGetSymbolAddress((void**)&py,    g_y);
    cudaGetSymbolAddress((void**)&pt1,   g_t1);
    cudaGetSymbolAddress((void**)&pt2,   g_t2);
    cudaGetSymbolAddress((void**)&pmean, g_mean);
    cudaGetSymbolAddress((void**)&pgate, g_gate);

    cudaFuncSetAttribute(flash_k, cudaFuncAttributeMaxDynamicSharedMemorySize,
                         FLASH_SMEM_BYTES);

    float* X = (float*)d_out;
    const int ROWS = B_ * N_;   // 8192

    for (int l = 0; l < 2; l++) {
        const float* w_qkv_l = w_qkv + (size_t)l * D_ * 3 * D_;
        const float* w_out_l = w_out + (size_t)l * D_ * D_;
        const float* b_out_l = b_out + (size_t)l * D_;
        const float* w_fc1_l = w_fc1 + (size_t)l * D_ * M_;
        const float* b_fc1_l = b_fc1 + (size_t)l * M_;
        const float* w_fc2_l = w_fc2 + (size_t)l * M_ * D_;
        const float* b_fc2_l = b_fc2 + (size_t)l * D_;
        const float* w1_l    = ls_w1 + (size_t)l * D_ * (D_/4);
        const float* w2_l    = ls_w2 + (size_t)l * (D_/4) * D_;

        // --- MHSA ---  (h = LN1(X); layer 0 fuses the initial copy)
        if (l == 0)
            copy_ln_k<<<ROWS, 256>>>(x_in, X, ln1_g, ln1_b, ph);

        // qkv = h @ w_qkv
        gemm4_k<128,128,false,0><<<dim3((3*D_)/128, ROWS/128, 1), 128>>>(
            ph, D_, 0, 0, w_qkv_l, 3*D_, 0, 0, pqkv, 3*D_, 0, 0,
            nullptr, D_, 1, 1.f);

        // fused attention: o = softmax(q k^T / 8) v
        flash_k<<<dim3(1, N_/FBM, B_*H_), 128, FLASH_SMEM_BYTES>>>(pqkv, po);

        // y = o @ w_out + b_out
        gemm4_k<128,128,false,0><<<dim3(D_/128, ROWS/128, 1), 128>>>(
            po, D_, 0, 0, w_out_l, D_, 0, 0, py, D_, 0, 0,
            b_out_l, D_, 1, 1.f);

        // lsrc #1 (fused)
        zero_k<<<(B_*D_ + 255)/256, 256>>>(pmean, B_*D_);
        add_colsum_k<<<B_ * (N_/128), 256>>>(X, py, pmean);
        gate_k<<<B_, 256>>>(pmean, w1_l, w2_l, pgate);
        scale_ln_k<<<ROWS, 256>>>(X, pgate, ln2_g + l * D_, ln2_b + l * D_, ph);

        // --- MLP ---
        gemm4_k<128,128,false,1><<<dim3(M_/128, ROWS/128, 1), 128>>>(
            ph, D_, 0, 0, w_fc1_l, M_, 0, 0, pt1, M_, 0, 0,
            b_fc1_l, D_, 1, 1.f);

        conv_k<<<(B_*N_*M_)/256, 256>>>(
            pt1, wh + (size_t)l*M_*3, bh + (size_t)l*M_,
            wv + (size_t)l*M_*3, bv + (size_t)l*M_,
            bn_g + (size_t)l*M_, bn_b + (size_t)l*M_,
            bn_m + (size_t)l*M_, bn_v + (size_t)l*M_, pt2);

        gemm4_k<128,128,false,0><<<dim3(D_/128, ROWS/128, 1), 128>>>(
            pt2, M_, 0, 0, w_fc2_l, D_, 0, 0, py, D_, 0, 0,
            b_fc2_l, M_, 1, 1.f);

        // lsrc #2 (fused); last one has no following LN
        zero_k<<<(B_*D_ + 255)/256, 256>>>(pmean, B_*D_);
        add_colsum_k<<<B_ * (N_/128), 256>>>(X, py, pmean);
        gate_k<<<B_, 256>>>(pmean, w1_l, w2_l, pgate);
        if (l + 1 < 2)
            scale_ln_k<<<ROWS, 256>>>(X, pgate, ln1_g + (l+1) * D_, ln1_b + (l+1) * D_, ph);
        else
            scale_k<<<(B_*N_*D_)/256, 256>>>(X, pgate);
    }
}